// round 13
// baseline (speedup 1.0000x reference)
#include <cuda_runtime.h>
#include <cuda_fp16.h>
#include <math.h>
#include <stdint.h>

// Problem constants
#define Bb   2
#define Ss   2048
#define Dd   1024
#define Hh   16
#define DKk  64
#define AUGC 192
#define ECOLS 576
#define XEXT 3072
#define BHh  (Bb * Hh)
#define Mm   (Bb * Ss)
#define NPART 32

// Scratch
__device__ float   g_Qaug[(size_t)BHh * Ss * AUGC];
__device__ float   g_Kaug[(size_t)BHh * Ss * AUGC];
__device__ __half  g_Qe16[(size_t)BHh * Ss * ECOLS];
__device__ __half  g_Ke16[(size_t)BHh * Ss * ECOLS];
__device__ __half  g_V16 [(size_t)BHh * DKk * Ss];
__device__ float   g_Freq[(size_t)BHh * 1025 * Ss];
__device__ __half  g_Xext[(size_t)Mm * XEXT];
__device__ __half  g_W16 [4][(size_t)Dd * XEXT];
__device__ __half  g_Oext[(size_t)Mm * XEXT];
__device__ float   g_pmax[(size_t)BHh * Ss * NPART];
__device__ float   g_psum[(size_t)BHh * Ss * NPART];
__device__ float   g_rowm[(size_t)BHh * Ss];
__device__ float   g_rowz[(size_t)BHh * Ss];
__device__ float2  g_twid[1024];

// ---------------------------------------------------------------------------
__device__ __forceinline__ uint32_t packh2(__half a, __half b) {
    __half2 p = __halves2half2(a, b);
    return *reinterpret_cast<uint32_t*>(&p);
}
__device__ __forceinline__ void mma_fp16(float c[4], const uint32_t a[4],
                                         const uint32_t b[2]) {
    asm volatile(
        "mma.sync.aligned.m16n8k16.row.col.f32.f16.f16.f32 "
        "{%0,%1,%2,%3}, {%4,%5,%6,%7}, {%8,%9}, {%0,%1,%2,%3};"
        : "+f"(c[0]), "+f"(c[1]), "+f"(c[2]), "+f"(c[3])
        : "r"(a[0]), "r"(a[1]), "r"(a[2]), "r"(a[3]), "r"(b[0]), "r"(b[1]));
}
__device__ __forceinline__ uint32_t smem_u32(const void* p) {
    uint32_t a;
    asm("{ .reg .u64 t; cvta.to.shared.u64 t, %1; cvt.u32.u64 %0, t; }"
        : "=r"(a) : "l"(p));
    return a;
}
__device__ __forceinline__ void ldmx4(uint32_t r[4], uint32_t addr) {
    asm volatile("ldmatrix.sync.aligned.m8n8.x4.shared.b16 {%0,%1,%2,%3}, [%4];"
        : "=r"(r[0]), "=r"(r[1]), "=r"(r[2]), "=r"(r[3]) : "r"(addr));
}
__device__ __forceinline__ void cp16(uint32_t sm, const void* g) {
    asm volatile("cp.async.ca.shared.global [%0], [%1], 16;"
                 :: "r"(sm), "l"(g) : "memory");
}
#define CPCOMMIT() asm volatile("cp.async.commit_group;" ::: "memory")
#define CPWAIT2()  asm volatile("cp.async.wait_group 2;" ::: "memory")

#define ALOFF(lane) (((lane) & 15) * 80 + (((lane) >> 4) & 1) * 16)
#define BLOFF(lane) (((((lane) >> 4) & 1) * 8 + ((lane) & 7)) * 80 + (((lane) >> 3) & 1) * 16)

// 6-stage ring: stage = A(128x80) + B(256x80) = 30720 B
#define APART 10240
#define STG   30720
#define SMPIPE (6 * STG)   // 184320

// ---------------------------------------------------------------------------
__global__ void twiddle_init_k() {
    int t = blockIdx.x * blockDim.x + threadIdx.x;
    if (t < 1024) {
        double ang = -2.0 * 3.14159265358979323846 * (double)t / 2048.0;
        double s, c;
        sincos(ang, &s, &c);
        g_twid[t] = make_float2((float)c, (float)s);
    }
}

// ---------------------------------------------------------------------------
__global__ __launch_bounds__(256)
void convx_k(const float* __restrict__ src, __half* __restrict__ dst)
{
    size_t i4 = (size_t)blockIdx.x * 256 + threadIdx.x;
    size_t row = i4 >> 8;
    int c = (int)(i4 & 255) * 4;
    float4 x = ((const float4*)src)[i4];

    __half hx = __float2half_rn(x.x), hy = __float2half_rn(x.y);
    __half hz = __float2half_rn(x.z), hw = __float2half_rn(x.w);
    uint2 H, L;
    H.x = packh2(hx, hy); H.y = packh2(hz, hw);
    L.x = packh2(__float2half_rn(x.x - __half2float(hx)),
                 __float2half_rn(x.y - __half2float(hy)));
    L.y = packh2(__float2half_rn(x.z - __half2float(hz)),
                 __float2half_rn(x.w - __half2float(hw)));

    __half* d = dst + row * XEXT;
    *(uint2*)(d + c) = H;
    *(uint2*)(d + 1024 + c) = L;
    *(uint2*)(d + 2048 + c) = H;
}

__global__ __launch_bounds__(256)
void convw_k(const float* __restrict__ Wq, const float* __restrict__ Wk,
             const float* __restrict__ Wv, const float* __restrict__ Wo)
{
    int z = blockIdx.y;
    const float* src = (z == 0) ? Wq : (z == 1) ? Wk : (z == 2) ? Wv : Wo;
    __half* dst = g_W16[z];

    size_t i4 = (size_t)blockIdx.x * 256 + threadIdx.x;
    size_t row = i4 >> 8;
    int c = (int)(i4 & 255) * 4;
    float4 x = ((const float4*)src)[i4];

    __half hx = __float2half_rn(x.x), hy = __float2half_rn(x.y);
    __half hz = __float2half_rn(x.z), hw = __float2half_rn(x.w);
    uint2 H, L;
    H.x = packh2(hx, hy); H.y = packh2(hz, hw);
    L.x = packh2(__float2half_rn(x.x - __half2float(hx)),
                 __float2half_rn(x.y - __half2float(hy)));
    L.y = packh2(__float2half_rn(x.z - __half2float(hz)),
                 __float2half_rn(x.w - __half2float(hw)));

    __half* d = dst + row * XEXT;
    *(uint2*)(d + c) = H;
    *(uint2*)(d + 1024 + c) = H;
    *(uint2*)(d + 2048 + c) = L;
}

// ---------------------------------------------------------------------------
// mma mainloop macro pieces (128x256 tile, 64x64 warps, 6-stage ring,
// 2 chunks per barrier)
// ---------------------------------------------------------------------------
#define MMA_CHUNK(aA, bA)                                                   \
    do {                                                                     \
        _Pragma("unroll")                                                    \
        for (int st = 0; st < 2; st++) {                                     \
            int kb = st * 32;                                                \
            uint32_t bfr[8][2];                                              \
            _Pragma("unroll")                                                \
            for (int nf2 = 0; nf2 < 4; nf2++) {                              \
                uint32_t r[4];                                               \
                ldmx4(r, (bA) + nf2 * (16 * 80) + kb);                       \
                bfr[nf2 * 2][0] = r[0]; bfr[nf2 * 2][1] = r[1];              \
                bfr[nf2 * 2 + 1][0] = r[2]; bfr[nf2 * 2 + 1][1] = r[3];      \
            }                                                                \
            _Pragma("unroll")                                                \
            for (int mf = 0; mf < 4; mf++) {                                 \
                uint32_t afr[4];                                             \
                ldmx4(afr, (aA) + mf * (16 * 80) + kb);                      \
                _Pragma("unroll")                                            \
                for (int nf = 0; nf < 8; nf++)                               \
                    mma_fp16(acc[mf][nf], afr, bfr[nf]);                     \
            }                                                                \
        }                                                                    \
    } while (0)

// ---------------------------------------------------------------------------
// Merged Q/K/V projection: grid (4, 32, 3)
// ---------------------------------------------------------------------------
__global__ __launch_bounds__(256, 1)
void gemm16qkv_k(const __half* __restrict__ Xe,
                 const float* __restrict__ bq, const float* __restrict__ bk,
                 const float* __restrict__ bv,
                 float* __restrict__ qaug, float* __restrict__ kaug,
                 __half* __restrict__ v16)
{
    extern __shared__ char smc[];

    const int tid  = threadIdx.x;
    const int wid  = tid >> 5;
    const int lane = tid & 31;
    const int g    = lane >> 2;
    const int tig  = lane & 3;
    const int wm   = wid >> 2;
    const int wn   = wid & 3;

    const int z  = blockIdx.z;
    const int m0 = blockIdx.y * 128;
    const int n0 = blockIdx.x * 256;

    const __half* Ag = Xe + (size_t)m0 * XEXT;
    const __half* Bg = g_W16[z] + (size_t)n0 * XEXT;
    const float* bias = (z == 0) ? bq : (z == 1) ? bk : bv;

    const uint32_t smb = smem_u32(smc);
    const uint32_t aAdr = smb + (wm * 64) * 80 + ALOFF(lane);
    const uint32_t bAdr = smb + APART + (wn * 64) * 80 + BLOFF(lane);

    const int lr = tid >> 2, lc16 = tid & 3;

    float acc[4][8][4];
#pragma unroll
    for (int mf = 0; mf < 4; mf++)
#pragma unroll
        for (int nf = 0; nf < 8; nf++)
#pragma unroll
            for (int j = 0; j < 4; j++) acc[mf][nf][j] = 0.f;

    const int NCH = XEXT / 32;   // 96
    auto issue = [&](int c) {
        if (c < NCH) {
            uint32_t sb = smb + (c % 6) * STG;
#pragma unroll
            for (int i = 0; i < 2; i++) {
                int r = lr + i * 64;
                cp16(sb + r * 80 + lc16 * 16,
                     Ag + (size_t)r * XEXT + c * 32 + lc16 * 8);
            }
#pragma unroll
            for (int i = 0; i < 4; i++) {
                int r = lr + i * 64;
                cp16(sb + APART + r * 80 + lc16 * 16,
                     Bg + (size_t)r * XEXT + c * 32 + lc16 * 8);
            }
        }
        CPCOMMIT();
    };

    issue(0); issue(1); issue(2); issue(3);

    for (int i = 0; i < NCH / 2; i++) {
        int c0 = 2 * i;
        CPWAIT2();
        __syncthreads();
        issue(c0 + 4);
        issue(c0 + 5);

        uint32_t aA = aAdr + (c0 % 6) * STG;
        uint32_t bA = bAdr + (c0 % 6) * STG;
        MMA_CHUNK(aA, bA);
        aA = aAdr + ((c0 + 1) % 6) * STG;
        bA = bAdr + ((c0 + 1) % 6) * STG;
        MMA_CHUNK(aA, bA);
    }

#pragma unroll
    for (int mf = 0; mf < 4; mf++) {
        int row0 = m0 + wm * 64 + mf * 16 + g;
#pragma unroll
        for (int nf = 0; nf < 8; nf++) {
            int n = n0 + wn * 64 + nf * 8 + tig * 2;
            float bx = bias[n], by = bias[n + 1];
#pragma unroll
            for (int hf = 0; hf < 2; hf++) {
                int m = row0 + hf * 8;
                float vx = acc[mf][nf][hf * 2] + bx;
                float vy = acc[mf][nf][hf * 2 + 1] + by;
                int bb = m >> 11, s = m & 2047;
                int hh = n >> 6,  d = n & 63;
                if (z < 2) {
                    float* aug = (z == 0) ? qaug : kaug;
                    *(float2*)(aug +
                        ((size_t)((bb * 16 + hh) * 2048 + s)) * AUGC + d) =
                        make_float2(vx, vy);
                } else {
                    __half* vp = v16
                        + ((size_t)(bb * 16 + hh) * 64 + d) * 2048 + s;
                    vp[0]    = __float2half_rn(vx);
                    vp[2048] = __float2half_rn(vy);
                }
            }
        }
    }
}

// ---------------------------------------------------------------------------
// Out projection: grid (4, 32)
// ---------------------------------------------------------------------------
__global__ __launch_bounds__(256, 1)
void gemm16o_k(const __half* __restrict__ Ae, const float* __restrict__ bias,
               float* __restrict__ C)
{
    extern __shared__ char smc[];

    const int tid  = threadIdx.x;
    const int wid  = tid >> 5;
    const int lane = tid & 31;
    const int g    = lane >> 2;
    const int tig  = lane & 3;
    const int wm   = wid >> 2;
    const int wn   = wid & 3;

    const int m0 = blockIdx.y * 128;
    const int n0 = blockIdx.x * 256;

    const __half* Ag = Ae + (size_t)m0 * XEXT;
    const __half* Bg = g_W16[3] + (size_t)n0 * XEXT;

    const uint32_t smb = smem_u32(smc);
    const uint32_t aAdr = smb + (wm * 64) * 80 + ALOFF(lane);
    const uint32_t bAdr = smb + APART + (wn * 64) * 80 + BLOFF(lane);

    const int lr = tid >> 2, lc16 = tid & 3;

    float acc[4][8][4];
#pragma unroll
    for (int mf = 0; mf < 4; mf++)
#pragma unroll
        for (int nf = 0; nf < 8; nf++)
#pragma unroll
            for (int j = 0; j < 4; j++) acc[mf][nf][j] = 0.f;

    const int NCH = XEXT / 32;
    auto issue = [&](int c) {
        if (c < NCH) {
            uint32_t sb = smb + (c % 6) * STG;
#pragma unroll
            for (int i = 0; i < 2; i++) {
                int r = lr + i * 64;
                cp16(sb + r * 80 + lc16 * 16,
                     Ag + (size_t)r * XEXT + c * 32 + lc16 * 8);
            }
#pragma unroll
            for (int i = 0; i < 4; i++) {
                int r = lr + i * 64;
                cp16(sb + APART + r * 80 + lc16 * 16,
                     Bg + (size_t)r * XEXT + c * 32 + lc16 * 8);
            }
        }
        CPCOMMIT();
    };

    issue(0); issue(1); issue(2); issue(3);

    for (int i = 0; i < NCH / 2; i++) {
        int c0 = 2 * i;
        CPWAIT2();
        __syncthreads();
        issue(c0 + 4);
        issue(c0 + 5);

        uint32_t aA = aAdr + (c0 % 6) * STG;
        uint32_t bA = bAdr + (c0 % 6) * STG;
        MMA_CHUNK(aA, bA);
        aA = aAdr + ((c0 + 1) % 6) * STG;
        bA = bAdr + ((c0 + 1) % 6) * STG;
        MMA_CHUNK(aA, bA);
    }

#pragma unroll
    for (int mf = 0; mf < 4; mf++) {
        int row0 = m0 + wm * 64 + mf * 16 + g;
#pragma unroll
        for (int nf = 0; nf < 8; nf++) {
            int n = n0 + wn * 64 + nf * 8 + tig * 2;
            float bx = bias[n], by = bias[n + 1];
#pragma unroll
            for (int hf = 0; hf < 2; hf++) {
                int m = row0 + hf * 8;
                *(float2*)(C + (size_t)m * Dd + n) =
                    make_float2(acc[mf][nf][hf * 2] + bx,
                                acc[mf][nf][hf * 2 + 1] + by);
            }
        }
    }
}

// ---------------------------------------------------------------------------
// FFT (known-good)
// ---------------------------------------------------------------------------
__global__ __launch_bounds__(256)
void fft_k(float* qaug, float* kaug, const float* twp, const float* fwp)
{
    __shared__ float  sr[2][2048];
    __shared__ float  si[2][2048];
    __shared__ float2 tw[1024];

    int bh     = blockIdx.x;
    int tensor = blockIdx.y;
    int dk0    = blockIdx.z * 2;
    float* base = (tensor == 0 ? qaug : kaug) + (size_t)bh * Ss * AUGC;
    int tid = threadIdx.x;

    for (int t = tid; t < 1024; t += 256) tw[t] = g_twid[t];

    for (int idx = tid; idx < 2 * Ss; idx += 256) {
        int l = idx & 1;
        int s = idx >> 1;
        float v = base[(size_t)s * AUGC + dk0 + l];
        int rs = __brev((unsigned)s) >> 21;
        sr[l][rs] = v;
        si[l][rs] = 0.f;
    }
    __syncthreads();

    for (int len = 2; len <= 2048; len <<= 1) {
        int half = len >> 1;
        int step = 2048 / len;
        for (int idx = tid; idx < 2048; idx += 256) {
            int l   = idx >> 10;
            int bix = idx & 1023;
            int grp = bix / half;
            int pos = bix - grp * half;
            int i0 = grp * len + pos;
            int i1 = i0 + half;
            float2 w = tw[pos * step];
            float xr = sr[l][i1], xi = si[l][i1];
            float tr = xr * w.x - xi * w.y;
            float ti = xr * w.y + xi * w.x;
            float ur = sr[l][i0], ui = si[l][i0];
            sr[l][i0] = ur + tr;  si[l][i0] = ui + ti;
            sr[l][i1] = ur - tr;  si[l][i1] = ui - ti;
        }
        __syncthreads();
    }

    float ft, ff;
    if (tensor == 0) { ft = twp[0] * 0.125f; ff = fwp[0] * 0.125f; }
    else             { ft = 1.f;             ff = 1.f; }

    for (int idx = tid; idx < 2 * Ss; idx += 256) {
        int l = idx & 1;
        int s = idx >> 1;
        size_t o = (size_t)s * AUGC + dk0 + l;
        if (tensor == 0) base[o] *= ft;
        base[o + 64]  = sr[l][s] * ff;
        base[o + 128] = si[l][s] * ff;
    }
}

// ---------------------------------------------------------------------------
template<int QMODE>
__global__ __launch_bounds__(256)
void convert16_k(const float* __restrict__ src, __half* __restrict__ dst)
{
    size_t i4 = (size_t)blockIdx.x * 256 + threadIdx.x;
    size_t row = i4 / 48;
    int c4 = (int)(i4 % 48);
    float4 x = ((const float4*)src)[i4];

    __half hx = __float2half_rn(x.x), hy = __float2half_rn(x.y);
    __half hz = __float2half_rn(x.z), hw = __float2half_rn(x.w);
    __half lx = __float2half_rn(x.x - __half2float(hx));
    __half ly = __float2half_rn(x.y - __half2float(hy));
    __half lz = __float2half_rn(x.z - __half2float(hz));
    __half lw = __float2half_rn(x.w - __half2float(hw));

    uint2 H, L;
    H.x = packh2(hx, hy); H.y = packh2(hz, hw);
    L.x = packh2(lx, ly); L.y = packh2(lz, lw);

    __half* drow = dst + row * ECOLS;
    int base, f, span;
    if (c4 < 16) { base = 0;   f = c4 * 4;      span = 64;  }
    else         { base = 192; f = c4 * 4 - 64; span = 128; }

    *(uint2*)(drow + base + f) = H;
    if (QMODE) {
        *(uint2*)(drow + base + span + f)     = L;
        *(uint2*)(drow + base + 2 * span + f) = H;
    } else {
        *(uint2*)(drow + base + span + f)     = H;
        *(uint2*)(drow + base + 2 * span + f) = L;
    }
}

// ---------------------------------------------------------------------------
// fp16 mma scores: 6-stage cp.async ring, 2 chunks/barrier.
// ---------------------------------------------------------------------------
template<int KOFF, int NCH, int EPI>
__global__ __launch_bounds__(256, 1)
void scores16_k(const __half* __restrict__ Qe, const __half* __restrict__ Ke,
                float* __restrict__ attn, float* __restrict__ Freq,
                float* __restrict__ pmax, float* __restrict__ psum)
{
    extern __shared__ char smc[];

    const int tid  = threadIdx.x;
    const int wid  = tid >> 5;
    const int lane = tid & 31;
    const int g    = lane >> 2;
    const int tig  = lane & 3;
    const int wm   = wid >> 2;
    const int wn   = wid & 3;

    const int ntile = blockIdx.x;
    const int mtile = blockIdx.y;
    const int bh    = blockIdx.z;
    const int m0 = mtile * 128;
    const int n0 = ntile * 256;

    const __half* Ag = Qe + ((size_t)bh * Ss + m0) * ECOLS + KOFF;
    const __half* Bg = Ke + ((size_t)bh * Ss + n0) * ECOLS + KOFF;

    const uint32_t smb = smem_u32(smc);
    const uint32_t aAdr = smb + (wm * 64) * 80 + ALOFF(lane);
    const uint32_t bAdr = smb + APART + (wn * 64) * 80 + BLOFF(lane);

    const int lr = tid >> 2, lc16 = tid & 3;

    float acc[4][8][4];
#pragma unroll
    for (int mf = 0; mf < 4; mf++)
#pragma unroll
        for (int nf = 0; nf < 8; nf++)
#pragma unroll
            for (int j = 0; j < 4; j++) acc[mf][nf][j] = 0.f;

    auto issue = [&](int c) {
        if (c < NCH) {
            uint32_t sb = smb + (c % 6) * STG;
#pragma unroll
            for (int i = 0; i < 2; i++) {
                int r = lr + i * 64;
                cp16(sb + r * 80 + lc16 * 16,
                     Ag + (size_t)r * ECOLS + c * 32 + lc16 * 8);
            }
#pragma unroll
            for (int i = 0; i < 4; i++) {
                int r = lr + i * 64;
                cp16(sb + APART + r * 80 + lc16 * 16,
                     Bg + (size_t)r * ECOLS + c * 32 + lc16 * 8);
            }
        }
        CPCOMMIT();
    };

    issue(0); issue(1); issue(2); issue(3);

    for (int i = 0; i < NCH / 2; i++) {
        int c0 = 2 * i;
        CPWAIT2();
        __syncthreads();
        issue(c0 + 4);
        issue(c0 + 5);

        uint32_t aA = aAdr + (c0 % 6) * STG;
        uint32_t bA = bAdr + (c0 % 6) * STG;
        MMA_CHUNK(aA, bA);
        aA = aAdr + ((c0 + 1) % 6) * STG;
        bA = bAdr + ((c0 + 1) % 6) * STG;
        MMA_CHUNK(aA, bA);
    }

    const int cbase = n0 + wn * 64 + tig * 2;

    if (EPI == 0) {
#pragma unroll
        for (int mf = 0; mf < 4; mf++) {
            int r0 = m0 + wm * 64 + mf * 16 + g;
#pragma unroll
            for (int hf = 0; hf < 2; hf++) {
                int r = r0 + hf * 8;
                if (r <= 1024) {
                    float* frow = Freq + ((size_t)bh * 1025 + r) * Ss;
#pragma unroll
                    for (int nf = 0; nf < 8; nf++)
                        *(float2*)(frow + cbase + nf * 8) =
                            make_float2(acc[mf][nf][hf * 2], acc[mf][nf][hf * 2 + 1]);
                }
            }
        }
    } else {
#pragma unroll
        for (int mf = 0; mf < 4; mf++) {
            int row0 = m0 + wm * 64 + mf * 16 + g;
#pragma unroll
            for (int hf = 0; hf < 2; hf++) {
                int r = row0 + hf * 8;
                if (r <= 1024) {
                    const float* fr = Freq + ((size_t)bh * 1025 + r) * Ss;
#pragma unroll
                    for (int nf = 0; nf < 8; nf++) {
                        float2 f = *(const float2*)(fr + cbase + nf * 8);
                        acc[mf][nf][hf * 2]     += f.x;
                        acc[mf][nf][hf * 2 + 1] += f.y;
                    }
                } else {
                    const float* fr = Freq + ((size_t)bh * 1025 + (2048 - r)) * Ss;
#pragma unroll
                    for (int nf = 0; nf < 8; nf++) {
                        int c0 = cbase + nf * 8;
                        acc[mf][nf][hf * 2]     += fr[(2048 - c0) & 2047];
                        acc[mf][nf][hf * 2 + 1] += fr[2047 - c0];
                    }
                }
            }

            float mx0 = -3.4e38f, mx1 = -3.4e38f;
#pragma unroll
            for (int nf = 0; nf < 8; nf++) {
                mx0 = fmaxf(mx0, fmaxf(acc[mf][nf][0], acc[mf][nf][1]));
                mx1 = fmaxf(mx1, fmaxf(acc[mf][nf][2], acc[mf][nf][3]));
            }
            mx0 = fmaxf(mx0, __shfl_xor_sync(0xffffffffu, mx0, 1));
            mx0 = fmaxf(mx0, __shfl_xor_sync(0xffffffffu, mx0, 2));
            mx1 = fmaxf(mx1, __shfl_xor_sync(0xffffffffu, mx1, 1));
            mx1 = fmaxf(mx1, __shfl_xor_sync(0xffffffffu, mx1, 2));

            float s0 = 0.f, s1 = 0.f;
#pragma unroll
            for (int nf = 0; nf < 8; nf++) {
                s0 += __expf(acc[mf][nf][0] - mx0) + __expf(acc[mf][nf][1] - mx0);
                s1 += __expf(acc[mf][nf][2] - mx1) + __expf(acc[mf][nf][3] - mx1);
            }
            s0 += __shfl_xor_sync(0xffffffffu, s0, 1);
            s0 += __shfl_xor_sync(0xffffffffu, s0, 2);
            s1 += __shfl_xor_sync(0xffffffffu, s1, 1);
            s1 += __shfl_xor_sync(0xffffffffu, s1, 2);

            if (tig == 0) {
                size_t gr0 = ((size_t)bh * Ss + row0) * NPART + ntile * 4 + wn;
                pmax[gr0] = mx0; psum[gr0] = s0;
                size_t gr1 = gr0 + 8 * NPART;
                pmax[gr1] = mx1; psum[gr1] = s1;
            }

            float* arow  = attn + ((size_t)bh << 22) + (size_t)row0 * Ss + cbase;
            float* arow8 = arow + 8 * Ss;
#pragma unroll
            for (int nf = 0; nf < 8; nf++)
                *(float2*)(arow + nf * 8) = make_float2(acc[mf][nf][0], acc[mf][nf][1]);
#pragma unroll
            for (int nf = 0; nf < 8; nf++)
                *(float2*)(arow8 + nf * 8) = make_float2(acc[mf][nf][2], acc[mf][nf][3]);
        }
    }
}

// ---------------------------------------------------------------------------
__global__ __launch_bounds__(256)
void combine_k(const float* __restrict__ pmax, const float* __restrict__ psum,
               float* __restrict__ rowm, float* __restrict__ rowz)
{
    int r = blockIdx.x * 256 + threadIdx.x;
    float m = -3.4e38f;
#pragma unroll
    for (int i = 0; i < NPART; i++) m = fmaxf(m, pmax[(size_t)r * NPART + i]);
    float z = 0.f;
#pragma unroll
    for (int i = 0; i < NPART; i++)
        z += psum[(size_t)r * NPART + i] * __expf(pmax[(size_t)r * NPART + i] - m);
    rowm[r] = m;
    rowz[r] = 1.f / z;
}

// ---------------------------------------------------------------------------
// Fused normalize + attn*V (R11, unchanged)
// ---------------------------------------------------------------------------
#define AVA (128 * 80)
#define AVB (64 * 80)

__global__ __launch_bounds__(256, 2)
void attnv16_k(float* __restrict__ attn, const __half* __restrict__ V16,
               const float* __restrict__ rowm, const float* __restrict__ rowz,
               __half* __restrict__ Oe)
{
    __shared__ char smc[2 * AVA + 2 * AVB];

    const int tid  = threadIdx.x;
    const int wid  = tid >> 5;
    const int lane = tid & 31;
    const int g    = lane >> 2;
    const int tig  = lane & 3;
    const int wm   = wid & 3;
    const int wn   = wid >> 2;

    const int mt = blockIdx.x, bh = blockIdx.y;
    const int m0 = mt * 128;
    float* Ab = attn + ((size_t)bh << 22) + (size_t)m0 * Ss;
    const __half* Vb = V16 + (size_t)bh * 64 * 2048;

    const int prow = tid >> 1;
    const int ph   = tid & 1;
    const float rm = rowm[bh * Ss + m0 + prow];
    const float rz = rowz[bh * Ss + m0 + prow];

    const int brow = tid >> 2;
    const int bq   = tid & 3;

    const uint32_t smb = smem_u32(smc);
    const uint32_t aAdr = smb + (wm * 32) * 80 + ALOFF(lane);
    const uint32_t bAdr = smb + 2 * AVA + (wn * 32) * 80 + BLOFF(lane);

    float acc[2][4][4];
#pragma unroll
    for (int mf = 0; mf < 2; mf++)
#pragma unroll
        for (int nf = 0; nf < 4; nf++)
#pragma unroll
            for (int j = 0; j < 4; j++) acc[mf][nf][j] = 0.f;

    float4 pa[4];
    uint4  vb;

    auto ldg = [&](int c) {
#pragma unroll
        for (int i = 0; i < 4; i++)
            pa[i] = *(const float4*)(Ab + (size_t)prow * Ss + c * 32 + ph * 16 + i * 4);
        vb = *(const uint4*)(Vb + (size_t)brow * 2048 + c * 32 + bq * 8);
    };
    auto sts = [&](int b, int c) {
        char* a16 = smc + b * AVA;
        float p[16];
#pragma unroll
        for (int i = 0; i < 4; i++) {
            p[4*i+0] = __expf(pa[i].x - rm) * rz;
            p[4*i+1] = __expf(pa[i].y - rm) * rz;
            p[4*i+2] = __expf(pa[i].z - rm) * rz;
            p[4*i+3] = __expf(pa[i].w - rm) * rz;
            *(float4*)(Ab + (size_t)prow * Ss + c * 32 + ph * 16 + i * 4) =
                make_float4(p[4*i+0], p[4*i+1], p[4*i+2], p[4*i+3]);
        }
        uint4 h0;
        h0.x = packh2(__float2half_rn(p[0]),  __float2half_rn(p[1]));
        h0.y = packh2(__float2half_rn(p[2]),  __float2half_rn(p[3]));
        h0.z = packh2(__float2half_rn(p[4]),  __float2half_rn(p[5]));
        h0.w = packh2(__float2half_rn(p[6]),  __float2half_rn(p[7]));
        uint4 h1;
        h1.x = packh2(__float2half_rn(p[8]),  __float2half_rn(p[9]));
        h1.y = packh2(__float2half_rn(p[10]), __float2half_rn(p[11]));
        h1.z = packh2(__float2half_rn(p[12]), __float2half_rn(p[13]));
        h1.w = packh2(__float2half_rn(p[14]), __float2half_rn(p[15]));
        char* arow = a16 + prow * 80 + ph * 32;
        *(uint4*)(arow)      = h0;
        *(uint4*)(arow + 16) = h1;
        char* b16 = smc + 2 * AVA + b * AVB;
        *(uint4*)(b16 + brow * 80 + bq * 16) = vb;
    };

    ldg(0);
    sts(0, 0);
    __syncthreads();

    const int NCH = 64;
    for (int c = 0; c < NCH; c++) {
        int buf = c & 1;
        if (c + 1 < NCH) ldg(c + 1);

        uint32_t aA = aAdr + buf * AVA;
        uint32_t bA = bAdr + buf * AVB;
#pragma unroll
        for (int st = 0; st < 2; st++) {
            int kb = st * 32;
            uint32_t bfr[4][2];
#pragma unroll
            for (int nf2 = 0; nf2 < 2; nf2++) {
                uint32_t r[4];
                ldmx4(r, bA + nf2 * (16 * 80) + kb);
                bfr[nf2 * 2][0] = r[0]; bfr[nf2 * 2][1] = r[1];
                bfr[nf2 * 2 + 1][0] = r[2]; bfr[nf2 * 2 + 1][1] = r[3];
            }
#pragma unroll
            for (int mf = 0; mf < 2; mf++) {
                uint32_t afr[4];
                ldmx4(afr, aA + mf * (16 * 80) + kb);
#pragma unroll
                for (int nf = 0; nf < 4; nf++)
                    mma_fp16(acc[mf][nf], afr, bfr[nf]);
            }
        }
        if (c + 1 < NCH) sts(buf ^ 1, c + 1);
        __syncthreads();
    }

    size_t rowbase = (size_t)(bh >> 4) * Ss + m0;
    int colbase = (bh & 15) * 64;
#pragma unroll
    for (int mf = 0; mf < 2; mf++) {
        int r0 = wm * 32 + mf * 16 + g;
#pragma unroll
        for (int nf = 0; nf < 4; nf++) {
            int col = colbase + wn * 32 + nf * 8 + tig * 2;
#pragma unroll
            for (int hf = 0; hf < 2; hf++) {
                float vx = acc[mf][nf][hf * 2], vy = acc[mf][nf][hf * 2 + 1];
                __half hx = __float2half_rn(vx), hy = __float2half_rn(vy);
                uint32_t H = packh2(hx, hy);
                uint32_t L = packh2(__float2half_rn(vx - __half2float(hx)),
                                    __float2half_rn(vy - __half2float(hy)));
                __half* orow = Oe + (rowbase + r0 + hf * 8) * XEXT;
                *(uint32_t*)(orow + col)        = H;
                *(uint32_t*)(orow + 1024 + col) = L;
                *(uint32_t*)(orow + 2048 + col) = H;
            }
        }
    }
}

// ---------------------------------------------------------------------------
extern "C" void kernel_launch(void* const* d_in, const int* in_sizes, int n_in,
                              void* d_out, int out_size)
{
    const float* x  = (const float*)d_in[0];
    const float* Wq = (const float*)d_in[1];
    const float* bq = (const float*)d_in[2];
    const float* Wk = (const float*)d_in[3];
    const float* bk = (const float*)d_in[4];
    const float* Wv = (const float*)d_in[5];
    const float* bv = (const float*)d_in[6];
    const float* Wo = (const float*)d_in[7];
    const float* bo = (const float*)d_in[8];
    const float* tw = (const float*)d_in[9];
    const float* fw = (const float*)d_in[10];

    float* out  = (float*)d_out;
    float* attn = out + (size_t)Mm * Dd;

    float *qaug, *kaug, *freq, *pmax, *psum, *rowm, *rowz;
    __half *qe, *ke, *v16, *xe, *oe;
    cudaGetSymbolAddress((void**)&qaug, g_Qaug);
    cudaGetSymbolAddress((void**)&kaug, g_Kaug);
    cudaGetSymbolAddress((void**)&qe,   g_Qe16);
    cudaGetSymbolAddress((void**)&ke,   g_Ke16);
    cudaGetSymbolAddress((void**)&v16,  g_V16);
    cudaGetSymbolAddress((void**)&freq, g_Freq);
    cudaGetSymbolAddress((void**)&xe,   g_Xext);
    cudaGetSymbolAddress((void**)&oe,   g_Oext);
    cudaGetSymbolAddress((void**)&pmax, g_pmax);
    cudaGetSymbolAddress((void**)&psum, g_psum);
    cudaGetSymbolAddress((void**)&rowm, g_rowm);
    cudaGetSymbolAddress((void**)&rowz, g_rowz);

    cudaFuncSetAttribute(scores16_k<192, 12, 0>,
                         cudaFuncAttributeMaxDynamicSharedMemorySize, SMPIPE);
    cudaFuncSetAttribute(scores16_k<0, 6, 1>,
                         cudaFuncAttributeMaxDynamicSharedMemorySize, SMPIPE);
    cudaFuncSetAttribute(gemm16qkv_k, cudaFuncAttributeMaxDynamicSharedMemorySize, SMPIPE);
    cudaFuncSetAttribute(gemm16o_k,   cudaFuncAttributeMaxDynamicSharedMemorySize, SMPIPE);

    dim3 blk(256);

    twiddle_init_k<<<4, 256>>>();

    // ext conversions
    convx_k<<<Mm, 256>>>(x, xe);
    convw_k<<<dim3(Dd, 4), 256>>>(Wq, Wk, Wv, Wo);

    // merged Q/K/V projections
    gemm16qkv_k<<<dim3(4, 32, 3), blk, SMPIPE>>>(xe, bq, bk, bv, qaug, kaug, v16);

    // FFT
    fft_k<<<dim3(BHh, 2, 32), blk>>>(qaug, kaug, tw, fw);

    // fp16x2 split for scores
    {
        int nblk = (int)(((size_t)BHh * Ss * 48) / 256);
        convert16_k<1><<<nblk, 256>>>(qaug, qe);
        convert16_k<0><<<nblk, 256>>>(kaug, ke);
    }

    // freq scores rows 0..1024 -> staged
    scores16_k<192, 12, 0><<<dim3(8, 9, BHh), blk, SMPIPE>>>(qe, ke, attn, freq, pmax, psum);

    // time scores + freq add + softmax partials
    scores16_k<0, 6, 1><<<dim3(8, 16, BHh), blk, SMPIPE>>>(qe, ke, attn, freq, pmax, psum);

    // combine partials
    combine_k<<<(BHh * Ss) / 256, 256>>>(pmax, psum, rowm, rowz);

    // fused normalize + attn*V
    attnv16_k<<<dim3(16, BHh), blk>>>(attn, v16, rowm, rowz, oe);

    // out projection
    gemm16o_k<<<dim3(4, 32), blk, SMPIPE>>>(oe, bo, out);
}

// round 14
// speedup vs baseline: 1.0046x; 1.0046x over previous
#include <cuda_runtime.h>
#include <cuda_fp16.h>
#include <math.h>
#include <stdint.h>

// Problem constants
#define Bb   2
#define Ss   2048
#define Dd   1024
#define Hh   16
#define DKk  64
#define AUGC 192
#define ECOLS 576
#define XEXT 3072
#define BHh  (Bb * Hh)
#define Mm   (Bb * Ss)
#define NPART 32

// Scratch
__device__ float   g_Qaug[(size_t)BHh * Ss * AUGC];
__device__ float   g_Kaug[(size_t)BHh * Ss * AUGC];
__device__ __half  g_Qe16[(size_t)BHh * Ss * ECOLS];
__device__ __half  g_Ke16[(size_t)BHh * Ss * ECOLS];
__device__ __half  g_V16 [(size_t)BHh * DKk * Ss];
__device__ float   g_Freq[(size_t)BHh * 1025 * Ss];
__device__ __half  g_Xext[(size_t)Mm * XEXT];
__device__ __half  g_W16 [4][(size_t)Dd * XEXT];
__device__ __half  g_Oext[(size_t)Mm * XEXT];
__device__ float   g_pmax[(size_t)BHh * Ss * NPART];
__device__ float   g_psum[(size_t)BHh * Ss * NPART];
__device__ float   g_rowm[(size_t)BHh * Ss];
__device__ float   g_rowz[(size_t)BHh * Ss];
__device__ float2  g_twid[1024];

// ---------------------------------------------------------------------------
__device__ __forceinline__ uint32_t packh2(__half a, __half b) {
    __half2 p = __halves2half2(a, b);
    return *reinterpret_cast<uint32_t*>(&p);
}
__device__ __forceinline__ void mma_fp16(float c[4], const uint32_t a[4],
                                         const uint32_t b[2]) {
    asm volatile(
        "mma.sync.aligned.m16n8k16.row.col.f32.f16.f16.f32 "
        "{%0,%1,%2,%3}, {%4,%5,%6,%7}, {%8,%9}, {%0,%1,%2,%3};"
        : "+f"(c[0]), "+f"(c[1]), "+f"(c[2]), "+f"(c[3])
        : "r"(a[0]), "r"(a[1]), "r"(a[2]), "r"(a[3]), "r"(b[0]), "r"(b[1]));
}
__device__ __forceinline__ uint32_t smem_u32(const void* p) {
    uint32_t a;
    asm("{ .reg .u64 t; cvta.to.shared.u64 t, %1; cvt.u32.u64 %0, t; }"
        : "=r"(a) : "l"(p));
    return a;
}
__device__ __forceinline__ void ldmx4(uint32_t r[4], uint32_t addr) {
    asm volatile("ldmatrix.sync.aligned.m8n8.x4.shared.b16 {%0,%1,%2,%3}, [%4];"
        : "=r"(r[0]), "=r"(r[1]), "=r"(r[2]), "=r"(r[3]) : "r"(addr));
}
__device__ __forceinline__ void cp16(uint32_t sm, const void* g) {
    asm volatile("cp.async.ca.shared.global [%0], [%1], 16;"
                 :: "r"(sm), "l"(g) : "memory");
}
#define CPCOMMIT() asm volatile("cp.async.commit_group;" ::: "memory")
#define CPWAIT1()  asm volatile("cp.async.wait_group 1;" ::: "memory")

#define ALOFF(lane) (((lane) & 15) * 80 + (((lane) >> 4) & 1) * 16)
#define BLOFF(lane) (((((lane) >> 4) & 1) * 8 + ((lane) & 7)) * 80 + (((lane) >> 3) & 1) * 16)

// 3-stage ring: stage = A(128x80) + B(256x80) = 30720 B
#define APART 10240
#define STG   30720
#define SMPIPE (3 * STG)   // 92160

// ---------------------------------------------------------------------------
__global__ void twiddle_init_k() {
    int t = blockIdx.x * blockDim.x + threadIdx.x;
    if (t < 1024) {
        double ang = -2.0 * 3.14159265358979323846 * (double)t / 2048.0;
        double s, c;
        sincos(ang, &s, &c);
        g_twid[t] = make_float2((float)c, (float)s);
    }
}

// ---------------------------------------------------------------------------
__global__ __launch_bounds__(256)
void convx_k(const float* __restrict__ src, __half* __restrict__ dst)
{
    size_t i4 = (size_t)blockIdx.x * 256 + threadIdx.x;
    size_t row = i4 >> 8;
    int c = (int)(i4 & 255) * 4;
    float4 x = ((const float4*)src)[i4];

    __half hx = __float2half_rn(x.x), hy = __float2half_rn(x.y);
    __half hz = __float2half_rn(x.z), hw = __float2half_rn(x.w);
    uint2 H, L;
    H.x = packh2(hx, hy); H.y = packh2(hz, hw);
    L.x = packh2(__float2half_rn(x.x - __half2float(hx)),
                 __float2half_rn(x.y - __half2float(hy)));
    L.y = packh2(__float2half_rn(x.z - __half2float(hz)),
                 __float2half_rn(x.w - __half2float(hw)));

    __half* d = dst + row * XEXT;
    *(uint2*)(d + c) = H;
    *(uint2*)(d + 1024 + c) = L;
    *(uint2*)(d + 2048 + c) = H;
}

__global__ __launch_bounds__(256)
void convw_k(const float* __restrict__ Wq, const float* __restrict__ Wk,
             const float* __restrict__ Wv, const float* __restrict__ Wo)
{
    int z = blockIdx.y;
    const float* src = (z == 0) ? Wq : (z == 1) ? Wk : (z == 2) ? Wv : Wo;
    __half* dst = g_W16[z];

    size_t i4 = (size_t)blockIdx.x * 256 + threadIdx.x;
    size_t row = i4 >> 8;
    int c = (int)(i4 & 255) * 4;
    float4 x = ((const float4*)src)[i4];

    __half hx = __float2half_rn(x.x), hy = __float2half_rn(x.y);
    __half hz = __float2half_rn(x.z), hw = __float2half_rn(x.w);
    uint2 H, L;
    H.x = packh2(hx, hy); H.y = packh2(hz, hw);
    L.x = packh2(__float2half_rn(x.x - __half2float(hx)),
                 __float2half_rn(x.y - __half2float(hy)));
    L.y = packh2(__float2half_rn(x.z - __half2float(hz)),
                 __float2half_rn(x.w - __half2float(hw)));

    __half* d = dst + row * XEXT;
    *(uint2*)(d + c) = H;
    *(uint2*)(d + 1024 + c) = H;
    *(uint2*)(d + 2048 + c) = L;
}

// ---------------------------------------------------------------------------
// Merged Q/K/V projection: cp.async 3-stage, 128x256 tile, ldmatrix.
// grid (4, 32, 3)
// ---------------------------------------------------------------------------
__global__ __launch_bounds__(256, 1)
void gemm16qkv_k(const __half* __restrict__ Xe,
                 const float* __restrict__ bq, const float* __restrict__ bk,
                 const float* __restrict__ bv,
                 float* __restrict__ qaug, float* __restrict__ kaug,
                 __half* __restrict__ v16)
{
    extern __shared__ char smc[];

    const int tid  = threadIdx.x;
    const int wid  = tid >> 5;
    const int lane = tid & 31;
    const int g    = lane >> 2;
    const int tig  = lane & 3;
    const int wm   = wid >> 2;
    const int wn   = wid & 3;

    const int z  = blockIdx.z;
    const int m0 = blockIdx.y * 128;
    const int n0 = blockIdx.x * 256;

    const __half* Ag = Xe + (size_t)m0 * XEXT;
    const __half* Bg = g_W16[z] + (size_t)n0 * XEXT;
    const float* bias = (z == 0) ? bq : (z == 1) ? bk : bv;

    const uint32_t smb = smem_u32(smc);
    const uint32_t aAdr = smb + (wm * 64) * 80 + ALOFF(lane);
    const uint32_t bAdr = smb + APART + (wn * 64) * 80 + BLOFF(lane);

    const int lr = tid >> 2, lc16 = tid & 3;

    float acc[4][8][4];
#pragma unroll
    for (int mf = 0; mf < 4; mf++)
#pragma unroll
        for (int nf = 0; nf < 8; nf++)
#pragma unroll
            for (int j = 0; j < 4; j++) acc[mf][nf][j] = 0.f;

    const int NCH = XEXT / 32;   // 96
    auto issue = [&](int c) {
        if (c < NCH) {
            uint32_t sb = smb + (c % 3) * STG;
#pragma unroll
            for (int i = 0; i < 2; i++) {
                int r = lr + i * 64;
                cp16(sb + r * 80 + lc16 * 16,
                     Ag + (size_t)r * XEXT + c * 32 + lc16 * 8);
            }
#pragma unroll
            for (int i = 0; i < 4; i++) {
                int r = lr + i * 64;
                cp16(sb + APART + r * 80 + lc16 * 16,
                     Bg + (size_t)r * XEXT + c * 32 + lc16 * 8);
            }
        }
        CPCOMMIT();
    };

    issue(0);
    issue(1);

    for (int c = 0; c < NCH; c++) {
        CPWAIT1();
        __syncthreads();
        issue(c + 2);

        uint32_t aA = aAdr + (c % 3) * STG;
        uint32_t bA = bAdr + (c % 3) * STG;
#pragma unroll
        for (int st = 0; st < 2; st++) {
            int kb = st * 32;
            uint32_t bfr[8][2];
#pragma unroll
            for (int nf2 = 0; nf2 < 4; nf2++) {
                uint32_t r[4];
                ldmx4(r, bA + nf2 * (16 * 80) + kb);
                bfr[nf2 * 2][0] = r[0]; bfr[nf2 * 2][1] = r[1];
                bfr[nf2 * 2 + 1][0] = r[2]; bfr[nf2 * 2 + 1][1] = r[3];
            }
#pragma unroll
            for (int mf = 0; mf < 4; mf++) {
                uint32_t afr[4];
                ldmx4(afr, aA + mf * (16 * 80) + kb);
#pragma unroll
                for (int nf = 0; nf < 8; nf++)
                    mma_fp16(acc[mf][nf], afr, bfr[nf]);
            }
        }
    }

#pragma unroll
    for (int mf = 0; mf < 4; mf++) {
        int row0 = m0 + wm * 64 + mf * 16 + g;
#pragma unroll
        for (int nf = 0; nf < 8; nf++) {
            int n = n0 + wn * 64 + nf * 8 + tig * 2;
            float bx = bias[n], by = bias[n + 1];
#pragma unroll
            for (int hf = 0; hf < 2; hf++) {
                int m = row0 + hf * 8;
                float vx = acc[mf][nf][hf * 2] + bx;
                float vy = acc[mf][nf][hf * 2 + 1] + by;
                int bb = m >> 11, s = m & 2047;
                int hh = n >> 6,  d = n & 63;
                if (z < 2) {
                    float* aug = (z == 0) ? qaug : kaug;
                    *(float2*)(aug +
                        ((size_t)((bb * 16 + hh) * 2048 + s)) * AUGC + d) =
                        make_float2(vx, vy);
                } else {
                    __half* vp = v16
                        + ((size_t)(bb * 16 + hh) * 64 + d) * 2048 + s;
                    vp[0]    = __float2half_rn(vx);
                    vp[2048] = __float2half_rn(vy);
                }
            }
        }
    }
}

// ---------------------------------------------------------------------------
// Out projection: same pipeline, grid (4, 32)
// ---------------------------------------------------------------------------
__global__ __launch_bounds__(256, 1)
void gemm16o_k(const __half* __restrict__ Ae, const float* __restrict__ bias,
               float* __restrict__ C)
{
    extern __shared__ char smc[];

    const int tid  = threadIdx.x;
    const int wid  = tid >> 5;
    const int lane = tid & 31;
    const int g    = lane >> 2;
    const int tig  = lane & 3;
    const int wm   = wid >> 2;
    const int wn   = wid & 3;

    const int m0 = blockIdx.y * 128;
    const int n0 = blockIdx.x * 256;

    const __half* Ag = Ae + (size_t)m0 * XEXT;
    const __half* Bg = g_W16[3] + (size_t)n0 * XEXT;

    const uint32_t smb = smem_u32(smc);
    const uint32_t aAdr = smb + (wm * 64) * 80 + ALOFF(lane);
    const uint32_t bAdr = smb + APART + (wn * 64) * 80 + BLOFF(lane);

    const int lr = tid >> 2, lc16 = tid & 3;

    float acc[4][8][4];
#pragma unroll
    for (int mf = 0; mf < 4; mf++)
#pragma unroll
        for (int nf = 0; nf < 8; nf++)
#pragma unroll
            for (int j = 0; j < 4; j++) acc[mf][nf][j] = 0.f;

    const int NCH = XEXT / 32;
    auto issue = [&](int c) {
        if (c < NCH) {
            uint32_t sb = smb + (c % 3) * STG;
#pragma unroll
            for (int i = 0; i < 2; i++) {
                int r = lr + i * 64;
                cp16(sb + r * 80 + lc16 * 16,
                     Ag + (size_t)r * XEXT + c * 32 + lc16 * 8);
            }
#pragma unroll
            for (int i = 0; i < 4; i++) {
                int r = lr + i * 64;
                cp16(sb + APART + r * 80 + lc16 * 16,
                     Bg + (size_t)r * XEXT + c * 32 + lc16 * 8);
            }
        }
        CPCOMMIT();
    };

    issue(0);
    issue(1);

    for (int c = 0; c < NCH; c++) {
        CPWAIT1();
        __syncthreads();
        issue(c + 2);

        uint32_t aA = aAdr + (c % 3) * STG;
        uint32_t bA = bAdr + (c % 3) * STG;
#pragma unroll
        for (int st = 0; st < 2; st++) {
            int kb = st * 32;
            uint32_t bfr[8][2];
#pragma unroll
            for (int nf2 = 0; nf2 < 4; nf2++) {
                uint32_t r[4];
                ldmx4(r, bA + nf2 * (16 * 80) + kb);
                bfr[nf2 * 2][0] = r[0]; bfr[nf2 * 2][1] = r[1];
                bfr[nf2 * 2 + 1][0] = r[2]; bfr[nf2 * 2 + 1][1] = r[3];
            }
#pragma unroll
            for (int mf = 0; mf < 4; mf++) {
                uint32_t afr[4];
                ldmx4(afr, aA + mf * (16 * 80) + kb);
#pragma unroll
                for (int nf = 0; nf < 8; nf++)
                    mma_fp16(acc[mf][nf], afr, bfr[nf]);
            }
        }
    }

#pragma unroll
    for (int mf = 0; mf < 4; mf++) {
        int row0 = m0 + wm * 64 + mf * 16 + g;
#pragma unroll
        for (int nf = 0; nf < 8; nf++) {
            int n = n0 + wn * 64 + nf * 8 + tig * 2;
            float bx = bias[n], by = bias[n + 1];
#pragma unroll
            for (int hf = 0; hf < 2; hf++) {
                int m = row0 + hf * 8;
                *(float2*)(C + (size_t)m * Dd + n) =
                    make_float2(acc[mf][nf][hf * 2] + bx,
                                acc[mf][nf][hf * 2 + 1] + by);
            }
        }
    }
}

// ---------------------------------------------------------------------------
// FFT (known-good)
// ---------------------------------------------------------------------------
__global__ __launch_bounds__(256)
void fft_k(float* qaug, float* kaug, const float* twp, const float* fwp)
{
    __shared__ float  sr[2][2048];
    __shared__ float  si[2][2048];
    __shared__ float2 tw[1024];

    int bh     = blockIdx.x;
    int tensor = blockIdx.y;
    int dk0    = blockIdx.z * 2;
    float* base = (tensor == 0 ? qaug : kaug) + (size_t)bh * Ss * AUGC;
    int tid = threadIdx.x;

    for (int t = tid; t < 1024; t += 256) tw[t] = g_twid[t];

    for (int idx = tid; idx < 2 * Ss; idx += 256) {
        int l = idx & 1;
        int s = idx >> 1;
        float v = base[(size_t)s * AUGC + dk0 + l];
        int rs = __brev((unsigned)s) >> 21;
        sr[l][rs] = v;
        si[l][rs] = 0.f;
    }
    __syncthreads();

    for (int len = 2; len <= 2048; len <<= 1) {
        int half = len >> 1;
        int step = 2048 / len;
        for (int idx = tid; idx < 2048; idx += 256) {
            int l   = idx >> 10;
            int bix = idx & 1023;
            int grp = bix / half;
            int pos = bix - grp * half;
            int i0 = grp * len + pos;
            int i1 = i0 + half;
            float2 w = tw[pos * step];
            float xr = sr[l][i1], xi = si[l][i1];
            float tr = xr * w.x - xi * w.y;
            float ti = xr * w.y + xi * w.x;
            float ur = sr[l][i0], ui = si[l][i0];
            sr[l][i0] = ur + tr;  si[l][i0] = ui + ti;
            sr[l][i1] = ur - tr;  si[l][i1] = ui - ti;
        }
        __syncthreads();
    }

    float ft, ff;
    if (tensor == 0) { ft = twp[0] * 0.125f; ff = fwp[0] * 0.125f; }
    else             { ft = 1.f;             ff = 1.f; }

    for (int idx = tid; idx < 2 * Ss; idx += 256) {
        int l = idx & 1;
        int s = idx >> 1;
        size_t o = (size_t)s * AUGC + dk0 + l;
        if (tensor == 0) base[o] *= ft;
        base[o + 64]  = sr[l][s] * ff;
        base[o + 128] = si[l][s] * ff;
    }
}

// ---------------------------------------------------------------------------
template<int QMODE>
__global__ __launch_bounds__(256)
void convert16_k(const float* __restrict__ src, __half* __restrict__ dst)
{
    size_t i4 = (size_t)blockIdx.x * 256 + threadIdx.x;
    size_t row = i4 / 48;
    int c4 = (int)(i4 % 48);
    float4 x = ((const float4*)src)[i4];

    __half hx = __float2half_rn(x.x), hy = __float2half_rn(x.y);
    __half hz = __float2half_rn(x.z), hw = __float2half_rn(x.w);
    __half lx = __float2half_rn(x.x - __half2float(hx));
    __half ly = __float2half_rn(x.y - __half2float(hy));
    __half lz = __float2half_rn(x.z - __half2float(hz));
    __half lw = __float2half_rn(x.w - __half2float(hw));

    uint2 H, L;
    H.x = packh2(hx, hy); H.y = packh2(hz, hw);
    L.x = packh2(lx, ly); L.y = packh2(lz, lw);

    __half* drow = dst + row * ECOLS;
    int base, f, span;
    if (c4 < 16) { base = 0;   f = c4 * 4;      span = 64;  }
    else         { base = 192; f = c4 * 4 - 64; span = 128; }

    *(uint2*)(drow + base + f) = H;
    if (QMODE) {
        *(uint2*)(drow + base + span + f)     = L;
        *(uint2*)(drow + base + 2 * span + f) = H;
    } else {
        *(uint2*)(drow + base + span + f)     = H;
        *(uint2*)(drow + base + 2 * span + f) = L;
    }
}

// ---------------------------------------------------------------------------
// Row-1024 freq scores (self-mirror row): fp32 dot over the 384-wide fp16 ext.
// grid (8, 32), 256 threads; one column per thread.
// ---------------------------------------------------------------------------
__global__ __launch_bounds__(256)
void freq1024_k(const __half* __restrict__ Qe, const __half* __restrict__ Ke,
                float* __restrict__ Freq)
{
    __shared__ __half qs[384];
    int bh = blockIdx.y;
    int c  = blockIdx.x * 256 + threadIdx.x;
    const __half* qrow = Qe + ((size_t)bh * Ss + 1024) * ECOLS + 192;
    for (int i = threadIdx.x; i < 384; i += 256) qs[i] = qrow[i];
    __syncthreads();
    const __half* krow = Ke + ((size_t)bh * Ss + c) * ECOLS + 192;
    float sum = 0.f;
#pragma unroll 8
    for (int k = 0; k < 384; k++)
        sum = fmaf(__half2float(qs[k]), __half2float(krow[k]), sum);
    Freq[((size_t)bh * 1025 + 1024) * Ss + c] = sum;
}

// ---------------------------------------------------------------------------
// fp16 mma scores: cp.async 3-stage + ldmatrix, 128x256 tile (R12 geometry).
// EPI=0 (freq): grid (8, 8, 32), rows 0..1023 staged.
// EPI=1 (time): grid (8, 16, 32).
// ---------------------------------------------------------------------------
template<int KOFF, int NCH, int EPI>
__global__ __launch_bounds__(256, 1)
void scores16_k(const __half* __restrict__ Qe, const __half* __restrict__ Ke,
                float* __restrict__ attn, float* __restrict__ Freq,
                float* __restrict__ pmax, float* __restrict__ psum)
{
    extern __shared__ char smc[];

    const int tid  = threadIdx.x;
    const int wid  = tid >> 5;
    const int lane = tid & 31;
    const int g    = lane >> 2;
    const int tig  = lane & 3;
    const int wm   = wid >> 2;
    const int wn   = wid & 3;

    const int ntile = blockIdx.x;
    const int mtile = blockIdx.y;
    const int bh    = blockIdx.z;
    const int m0 = mtile * 128;
    const int n0 = ntile * 256;

    const __half* Ag = Qe + ((size_t)bh * Ss + m0) * ECOLS + KOFF;
    const __half* Bg = Ke + ((size_t)bh * Ss + n0) * ECOLS + KOFF;

    const uint32_t smb = smem_u32(smc);
    const uint32_t aAdr = smb + (wm * 64) * 80 + ALOFF(lane);
    const uint32_t bAdr = smb + APART + (wn * 64) * 80 + BLOFF(lane);

    const int lr = tid >> 2, lc16 = tid & 3;

    float acc[4][8][4];
#pragma unroll
    for (int mf = 0; mf < 4; mf++)
#pragma unroll
        for (int nf = 0; nf < 8; nf++)
#pragma unroll
            for (int j = 0; j < 4; j++) acc[mf][nf][j] = 0.f;

    auto issue = [&](int c) {
        if (c < NCH) {
            uint32_t sb = smb + (c % 3) * STG;
#pragma unroll
            for (int i = 0; i < 2; i++) {
                int r = lr + i * 64;
                cp16(sb + r * 80 + lc16 * 16,
                     Ag + (size_t)r * ECOLS + c * 32 + lc16 * 8);
            }
#pragma unroll
            for (int i = 0; i < 4; i++) {
                int r = lr + i * 64;
                cp16(sb + APART + r * 80 + lc16 * 16,
                     Bg + (size_t)r * ECOLS + c * 32 + lc16 * 8);
            }
        }
        CPCOMMIT();
    };

    issue(0);
    issue(1);

    for (int c = 0; c < NCH; c++) {
        CPWAIT1();
        __syncthreads();
        issue(c + 2);

        uint32_t aA = aAdr + (c % 3) * STG;
        uint32_t bA = bAdr + (c % 3) * STG;
#pragma unroll
        for (int st = 0; st < 2; st++) {
            int kb = st * 32;
            uint32_t bfr[8][2];
#pragma unroll
            for (int nf2 = 0; nf2 < 4; nf2++) {
                uint32_t r[4];
                ldmx4(r, bA + nf2 * (16 * 80) + kb);
                bfr[nf2 * 2][0] = r[0]; bfr[nf2 * 2][1] = r[1];
                bfr[nf2 * 2 + 1][0] = r[2]; bfr[nf2 * 2 + 1][1] = r[3];
            }
#pragma unroll
            for (int mf = 0; mf < 4; mf++) {
                uint32_t afr[4];
                ldmx4(afr, aA + mf * (16 * 80) + kb);
#pragma unroll
                for (int nf = 0; nf < 8; nf++)
                    mma_fp16(acc[mf][nf], afr, bfr[nf]);
            }
        }
    }

    const int cbase = n0 + wn * 64 + tig * 2;

    if (EPI == 0) {
#pragma unroll
        for (int mf = 0; mf < 4; mf++) {
            int r0 = m0 + wm * 64 + mf * 16 + g;
#pragma unroll
            for (int hf = 0; hf < 2; hf++) {
                int r = r0 + hf * 8;
                float* frow = Freq + ((size_t)bh * 1025 + r) * Ss;
#pragma unroll
                for (int nf = 0; nf < 8; nf++)
                    *(float2*)(frow + cbase + nf * 8) =
                        make_float2(acc[mf][nf][hf * 2], acc[mf][nf][hf * 2 + 1]);
            }
        }
    } else {
#pragma unroll
        for (int mf = 0; mf < 4; mf++) {
            int row0 = m0 + wm * 64 + mf * 16 + g;
#pragma unroll
            for (int hf = 0; hf < 2; hf++) {
                int r = row0 + hf * 8;
                if (r <= 1024) {
                    const float* fr = Freq + ((size_t)bh * 1025 + r) * Ss;
#pragma unroll
                    for (int nf = 0; nf < 8; nf++) {
                        float2 f = *(const float2*)(fr + cbase + nf * 8);
                        acc[mf][nf][hf * 2]     += f.x;
                        acc[mf][nf][hf * 2 + 1] += f.y;
                    }
                } else {
                    const float* fr = Freq + ((size_t)bh * 1025 + (2048 - r)) * Ss;
#pragma unroll
                    for (int nf = 0; nf < 8; nf++) {
                        int c0 = cbase + nf * 8;
                        acc[mf][nf][hf * 2]     += fr[(2048 - c0) & 2047];
                        acc[mf][nf][hf * 2 + 1] += fr[2047 - c0];
                    }
                }
            }

            float mx0 = -3.4e38f, mx1 = -3.4e38f;
#pragma unroll
            for (int nf = 0; nf < 8; nf++) {
                mx0 = fmaxf(mx0, fmaxf(acc[mf][nf][0], acc[mf][nf][1]));
                mx1 = fmaxf(mx1, fmaxf(acc[mf][nf][2], acc[mf][nf][3]));
            }
            mx0 = fmaxf(mx0, __shfl_xor_sync(0xffffffffu, mx0, 1));
            mx0 = fmaxf(mx0, __shfl_xor_sync(0xffffffffu, mx0, 2));
            mx1 = fmaxf(mx1, __shfl_xor_sync(0xffffffffu, mx1, 1));
            mx1 = fmaxf(mx1, __shfl_xor_sync(0xffffffffu, mx1, 2));

            float s0 = 0.f, s1 = 0.f;
#pragma unroll
            for (int nf = 0; nf < 8; nf++) {
                s0 += __expf(acc[mf][nf][0] - mx0) + __expf(acc[mf][nf][1] - mx0);
                s1 += __expf(acc[mf][nf][2] - mx1) + __expf(acc[mf][nf][3] - mx1);
            }
            s0 += __shfl_xor_sync(0xffffffffu, s0, 1);
            s0 += __shfl_xor_sync(0xffffffffu, s0, 2);
            s1 += __shfl_xor_sync(0xffffffffu, s1, 1);
            s1 += __shfl_xor_sync(0xffffffffu, s1, 2);

            if (tig == 0) {
                size_t gr0 = ((size_t)bh * Ss + row0) * NPART + ntile * 4 + wn;
                pmax[gr0] = mx0; psum[gr0] = s0;
                size_t gr1 = gr0 + 8 * NPART;
                pmax[gr1] = mx1; psum[gr1] = s1;
            }

            float* arow  = attn + ((size_t)bh << 22) + (size_t)row0 * Ss + cbase;
            float* arow8 = arow + 8 * Ss;
#pragma unroll
            for (int nf = 0; nf < 8; nf++)
                *(float2*)(arow + nf * 8) = make_float2(acc[mf][nf][0], acc[mf][nf][1]);
#pragma unroll
            for (int nf = 0; nf < 8; nf++)
                *(float2*)(arow8 + nf * 8) = make_float2(acc[mf][nf][2], acc[mf][nf][3]);
        }
    }
}

// ---------------------------------------------------------------------------
__global__ __launch_bounds__(256)
void combine_k(const float* __restrict__ pmax, const float* __restrict__ psum,
               float* __restrict__ rowm, float* __restrict__ rowz)
{
    int r = blockIdx.x * 256 + threadIdx.x;
    float m = -3.4e38f;
#pragma unroll
    for (int i = 0; i < NPART; i++) m = fmaxf(m, pmax[(size_t)r * NPART + i]);
    float z = 0.f;
#pragma unroll
    for (int i = 0; i < NPART; i++)
        z += psum[(size_t)r * NPART + i] * __expf(pmax[(size_t)r * NPART + i] - m);
    rowm[r] = m;
    rowz[r] = 1.f / z;
}

// ---------------------------------------------------------------------------
// Fused normalize + attn*V (R11/R12 form)
// ---------------------------------------------------------------------------
#define AVA (128 * 80)
#define AVB (64 * 80)

__global__ __launch_bounds__(256, 2)
void attnv16_k(float* __restrict__ attn, const __half* __restrict__ V16,
               const float* __restrict__ rowm, const float* __restrict__ rowz,
               __half* __restrict__ Oe)
{
    __shared__ char smc[2 * AVA + 2 * AVB];

    const int tid  = threadIdx.x;
    const int wid  = tid >> 5;
    const int lane = tid & 31;
    const int g    = lane >> 2;
    const int tig  = lane & 3;
    const int wm   = wid & 3;
    const int wn   = wid >> 2;

    const int mt = blockIdx.x, bh = blockIdx.y;
    const int m0 = mt * 128;
    float* Ab = attn + ((size_t)bh << 22) + (size_t)m0 * Ss;
    const __half* Vb = V16 + (size_t)bh * 64 * 2048;

    const int prow = tid >> 1;
    const int ph   = tid & 1;
    const float rm = rowm[bh * Ss + m0 + prow];
    const float rz = rowz[bh * Ss + m0 + prow];

    const int brow = tid >> 2;
    const int bq   = tid & 3;

    const uint32_t smb = smem_u32(smc);
    const uint32_t aAdr = smb + (wm * 32) * 80 + ALOFF(lane);
    const uint32_t bAdr = smb + 2 * AVA + (wn * 32) * 80 + BLOFF(lane);

    float acc[2][4][4];
#pragma unroll
    for (int mf = 0; mf < 2; mf++)
#pragma unroll
        for (int nf = 0; nf < 4; nf++)
#pragma unroll
            for (int j = 0; j < 4; j++) acc[mf][nf][j] = 0.f;

    float4 pa[4];
    uint4  vb;

    auto ldg = [&](int c) {
#pragma unroll
        for (int i = 0; i < 4; i++)
            pa[i] = *(const float4*)(Ab + (size_t)prow * Ss + c * 32 + ph * 16 + i * 4);
        vb = *(const uint4*)(Vb + (size_t)brow * 2048 + c * 32 + bq * 8);
    };
    auto sts = [&](int b, int c) {
        char* a16 = smc + b * AVA;
        float p[16];
#pragma unroll
        for (int i = 0; i < 4; i++) {
            p[4*i+0] = __expf(pa[i].x - rm) * rz;
            p[4*i+1] = __expf(pa[i].y - rm) * rz;
            p[4*i+2] = __expf(pa[i].z - rm) * rz;
            p[4*i+3] = __expf(pa[i].w - rm) * rz;
            *(float4*)(Ab + (size_t)prow * Ss + c * 32 + ph * 16 + i * 4) =
                make_float4(p[4*i+0], p[4*i+1], p[4*i+2], p[4*i+3]);
        }
        uint4 h0;
        h0.x = packh2(__float2half_rn(p[0]),  __float2half_rn(p[1]));
        h0.y = packh2(__float2half_rn(p[2]),  __float2half_rn(p[3]));
        h0.z = packh2(__float2half_rn(p[4]),  __float2half_rn(p[5]));
        h0.w = packh2(__float2half_rn(p[6]),  __float2half_rn(p[7]));
        uint4 h1;
        h1.x = packh2(__float2half_rn(p[8]),  __float2half_rn(p[9]));
        h1.y = packh2(__float2half_rn(p[10]), __float2half_rn(p[11]));
        h1.z = packh2(__float2half_rn(p[12]), __float2half_rn(p[13]));
        h1.w = packh2(__float2half_rn(p[14]), __float2half_rn(p[15]));
        char* arow = a16 + prow * 80 + ph * 32;
        *(uint4*)(arow)      = h0;
        *(uint4*)(arow + 16) = h1;
        char* b16 = smc + 2 * AVA + b * AVB;
        *(uint4*)(b16 + brow * 80 + bq * 16) = vb;
    };

    ldg(0);
    sts(0, 0);
    __syncthreads();

    const int NCH = 64;
    for (int c = 0; c < NCH; c++) {
        int buf = c & 1;
        if (c + 1 < NCH) ldg(c + 1);

        uint32_t aA = aAdr + buf * AVA;
        uint32_t bA = bAdr + buf * AVB;
#pragma unroll
        for (int st = 0; st < 2; st++) {
            int kb = st * 32;
            uint32_t bfr[4][2];
#pragma unroll
            for (int nf2 = 0; nf2 < 2; nf2++) {
                uint32_t r[4];
                ldmx4(r, bA + nf2 * (16 * 80) + kb);
                bfr[nf2 * 2][0] = r[0]; bfr[nf2 * 2][1] = r[1];
                bfr[nf2 * 2 + 1][0] = r[2]; bfr[nf2 * 2 + 1][1] = r[3];
            }
#pragma unroll
            for (int mf = 0; mf < 2; mf++) {
                uint32_t afr[4];
                ldmx4(afr, aA + mf * (16 * 80) + kb);
#pragma unroll
                for (int nf = 0; nf < 4; nf++)
                    mma_fp16(acc[mf][nf], afr, bfr[nf]);
            }
        }
        if (c + 1 < NCH) sts(buf ^ 1, c + 1);
        __syncthreads();
    }

    size_t rowbase = (size_t)(bh >> 4) * Ss + m0;
    int colbase = (bh & 15) * 64;
#pragma unroll
    for (int mf = 0; mf < 2; mf++) {
        int r0 = wm * 32 + mf * 16 + g;
#pragma unroll
        for (int nf = 0; nf < 4; nf++) {
            int col = colbase + wn * 32 + nf * 8 + tig * 2;
#pragma unroll
            for (int hf = 0; hf < 2; hf++) {
                float vx = acc[mf][nf][hf * 2], vy = acc[mf][nf][hf * 2 + 1];
                __half hx = __float2half_rn(vx), hy = __float2half_rn(vy);
                uint32_t H = packh2(hx, hy);
                uint32_t L = packh2(__float2half_rn(vx - __half2float(hx)),
                                    __float2half_rn(vy - __half2float(hy)));
                __half* orow = Oe + (rowbase + r0 + hf * 8) * XEXT;
                *(uint32_t*)(orow + col)        = H;
                *(uint32_t*)(orow + 1024 + col) = L;
                *(uint32_t*)(orow + 2048 + col) = H;
            }
        }
    }
}

// ---------------------------------------------------------------------------
extern "C" void kernel_launch(void* const* d_in, const int* in_sizes, int n_in,
                              void* d_out, int out_size)
{
    const float* x  = (const float*)d_in[0];
    const float* Wq = (const float*)d_in[1];
    const float* bq = (const float*)d_in[2];
    const float* Wk = (const float*)d_in[3];
    const float* bk = (const float*)d_in[4];
    const float* Wv = (const float*)d_in[5];
    const float* bv = (const float*)d_in[6];
    const float* Wo = (const float*)d_in[7];
    const float* bo = (const float*)d_in[8];
    const float* tw = (const float*)d_in[9];
    const float* fw = (const float*)d_in[10];

    float* out  = (float*)d_out;
    float* attn = out + (size_t)Mm * Dd;

    float *qaug, *kaug, *freq, *pmax, *psum, *rowm, *rowz;
    __half *qe, *ke, *v16, *xe, *oe;
    cudaGetSymbolAddress((void**)&qaug, g_Qaug);
    cudaGetSymbolAddress((void**)&kaug, g_Kaug);
    cudaGetSymbolAddress((void**)&qe,   g_Qe16);
    cudaGetSymbolAddress((void**)&ke,   g_Ke16);
    cudaGetSymbolAddress((void**)&v16,  g_V16);
    cudaGetSymbolAddress((void**)&freq, g_Freq);
    cudaGetSymbolAddress((void**)&xe,   g_Xext);
    cudaGetSymbolAddress((void**)&oe,   g_Oext);
    cudaGetSymbolAddress((void**)&pmax, g_pmax);
    cudaGetSymbolAddress((void**)&psum, g_psum);
    cudaGetSymbolAddress((void**)&rowm, g_rowm);
    cudaGetSymbolAddress((void**)&rowz, g_rowz);

    cudaFuncSetAttribute(scores16_k<192, 12, 0>,
                         cudaFuncAttributeMaxDynamicSharedMemorySize, SMPIPE);
    cudaFuncSetAttribute(scores16_k<0, 6, 1>,
                         cudaFuncAttributeMaxDynamicSharedMemorySize, SMPIPE);
    cudaFuncSetAttribute(gemm16qkv_k, cudaFuncAttributeMaxDynamicSharedMemorySize, SMPIPE);
    cudaFuncSetAttribute(gemm16o_k,   cudaFuncAttributeMaxDynamicSharedMemorySize, SMPIPE);

    dim3 blk(256);

    twiddle_init_k<<<4, 256>>>();

    // ext conversions
    convx_k<<<Mm, 256>>>(x, xe);
    convw_k<<<dim3(Dd, 4), 256>>>(Wq, Wk, Wv, Wo);

    // merged Q/K/V projections
    gemm16qkv_k<<<dim3(4, 32, 3), blk, SMPIPE>>>(xe, bq, bk, bv, qaug, kaug, v16);

    // FFT
    fft_k<<<dim3(BHh, 2, 32), blk>>>(qaug, kaug, tw, fw);

    // fp16x2 split for scores
    {
        int nblk = (int)(((size_t)BHh * Ss * 48) / 256);
        convert16_k<1><<<nblk, 256>>>(qaug, qe);
        convert16_k<0><<<nblk, 256>>>(kaug, ke);
    }

    // freq scores rows 0..1023 (mma) + row 1024 (scalar, self-mirror)
    scores16_k<192, 12, 0><<<dim3(8, 8, BHh), blk, SMPIPE>>>(qe, ke, attn, freq, pmax, psum);
    freq1024_k<<<dim3(8, BHh), 256>>>(qe, ke, freq);

    // time scores + freq add + softmax partials
    scores16_k<0, 6, 1><<<dim3(8, 16, BHh), blk, SMPIPE>>>(qe, ke, attn, freq, pmax, psum);

    // combine partials
    combine_k<<<(BHh * Ss) / 256, 256>>>(pmax, psum, rowm, rowz);

    // fused normalize + attn*V
    attnv16_k<<<dim3(16, BHh), blk>>>(attn, v16, rowm, rowz, oe);

    // out projection
    gemm16o_k<<<dim3(4, 32), blk, SMPIPE>>>(oe, bo, out);
}

// round 15
// speedup vs baseline: 1.0826x; 1.0776x over previous
#include <cuda_runtime.h>
#include <cuda_fp16.h>
#include <math.h>
#include <stdint.h>

// Problem constants
#define Bb   2
#define Ss   2048
#define Dd   1024
#define Hh   16
#define DKk  64
#define AUGC 192
#define ECOLS 576
#define XEXT 3072
#define OEXT 2048             // O ext: [oh | oh] (lo correction dropped)
#define BHh  (Bb * Hh)
#define Mm   (Bb * Ss)
#define NPART 32

// Scratch
__device__ float   g_Qaug[(size_t)BHh * Ss * AUGC];
__device__ float   g_Kaug[(size_t)BHh * Ss * AUGC];
__device__ __half  g_Qe16[(size_t)BHh * Ss * ECOLS];
__device__ __half  g_Ke16[(size_t)BHh * Ss * ECOLS];
__device__ __half  g_V16 [(size_t)BHh * DKk * Ss];
__device__ float   g_Freq[(size_t)BHh * 1025 * Ss];
__device__ __half  g_Xext[(size_t)Mm * XEXT];
__device__ __half  g_W16 [4][(size_t)Dd * XEXT];
__device__ __half  g_Oext[(size_t)Mm * OEXT];
__device__ float   g_pmax[(size_t)BHh * Ss * NPART];
__device__ float   g_psum[(size_t)BHh * Ss * NPART];
__device__ float   g_rowm[(size_t)BHh * Ss];
__device__ float   g_rowz[(size_t)BHh * Ss];
__device__ float2  g_twid[1024];

// ---------------------------------------------------------------------------
__device__ __forceinline__ uint32_t packh2(__half a, __half b) {
    __half2 p = __halves2half2(a, b);
    return *reinterpret_cast<uint32_t*>(&p);
}
__device__ __forceinline__ void mma_fp16(float c[4], const uint32_t a[4],
                                         const uint32_t b[2]) {
    asm volatile(
        "mma.sync.aligned.m16n8k16.row.col.f32.f16.f16.f32 "
        "{%0,%1,%2,%3}, {%4,%5,%6,%7}, {%8,%9}, {%0,%1,%2,%3};"
        : "+f"(c[0]), "+f"(c[1]), "+f"(c[2]), "+f"(c[3])
        : "r"(a[0]), "r"(a[1]), "r"(a[2]), "r"(a[3]), "r"(b[0]), "r"(b[1]));
}
__device__ __forceinline__ uint32_t smem_u32(const void* p) {
    uint32_t a;
    asm("{ .reg .u64 t; cvta.to.shared.u64 t, %1; cvt.u32.u64 %0, t; }"
        : "=r"(a) : "l"(p));
    return a;
}
__device__ __forceinline__ void ldmx4(uint32_t r[4], uint32_t addr) {
    asm volatile("ldmatrix.sync.aligned.m8n8.x4.shared.b16 {%0,%1,%2,%3}, [%4];"
        : "=r"(r[0]), "=r"(r[1]), "=r"(r[2]), "=r"(r[3]) : "r"(addr));
}
__device__ __forceinline__ void cp16(uint32_t sm, const void* g) {
    asm volatile("cp.async.ca.shared.global [%0], [%1], 16;"
                 :: "r"(sm), "l"(g) : "memory");
}
#define CPCOMMIT() asm volatile("cp.async.commit_group;" ::: "memory")
#define CPWAIT1()  asm volatile("cp.async.wait_group 1;" ::: "memory")

#define ALOFF(lane) (((lane) & 15) * 80 + (((lane) >> 4) & 1) * 16)
#define BLOFF(lane) (((((lane) >> 4) & 1) * 8 + ((lane) & 7)) * 80 + (((lane) >> 3) & 1) * 16)

// 3-stage ring: stage = A(128x80) + B(256x80) = 30720 B
#define APART 10240
#define STG   30720
#define SMPIPE (3 * STG)   // 92160

// ---------------------------------------------------------------------------
__global__ void twiddle_init_k() {
    int t = blockIdx.x * blockDim.x + threadIdx.x;
    if (t < 1024) {
        double ang = -2.0 * 3.14159265358979323846 * (double)t / 2048.0;
        double s, c;
        sincos(ang, &s, &c);
        g_twid[t] = make_float2((float)c, (float)s);
    }
}

// ---------------------------------------------------------------------------
__global__ __launch_bounds__(256)
void convx_k(const float* __restrict__ src, __half* __restrict__ dst)
{
    size_t i4 = (size_t)blockIdx.x * 256 + threadIdx.x;
    size_t row = i4 >> 8;
    int c = (int)(i4 & 255) * 4;
    float4 x = ((const float4*)src)[i4];

    __half hx = __float2half_rn(x.x), hy = __float2half_rn(x.y);
    __half hz = __float2half_rn(x.z), hw = __float2half_rn(x.w);
    uint2 H, L;
    H.x = packh2(hx, hy); H.y = packh2(hz, hw);
    L.x = packh2(__float2half_rn(x.x - __half2float(hx)),
                 __float2half_rn(x.y - __half2float(hy)));
    L.y = packh2(__float2half_rn(x.z - __half2float(hz)),
                 __float2half_rn(x.w - __half2float(hw)));

    __half* d = dst + row * XEXT;
    *(uint2*)(d + c) = H;
    *(uint2*)(d + 1024 + c) = L;
    *(uint2*)(d + 2048 + c) = H;
}

__global__ __launch_bounds__(256)
void convw_k(const float* __restrict__ Wq, const float* __restrict__ Wk,
             const float* __restrict__ Wv, const float* __restrict__ Wo)
{
    int z = blockIdx.y;
    const float* src = (z == 0) ? Wq : (z == 1) ? Wk : (z == 2) ? Wv : Wo;
    __half* dst = g_W16[z];

    size_t i4 = (size_t)blockIdx.x * 256 + threadIdx.x;
    size_t row = i4 >> 8;
    int c = (int)(i4 & 255) * 4;
    float4 x = ((const float4*)src)[i4];

    __half hx = __float2half_rn(x.x), hy = __float2half_rn(x.y);
    __half hz = __float2half_rn(x.z), hw = __float2half_rn(x.w);
    uint2 H, L;
    H.x = packh2(hx, hy); H.y = packh2(hz, hw);
    L.x = packh2(__float2half_rn(x.x - __half2float(hx)),
                 __float2half_rn(x.y - __half2float(hy)));
    L.y = packh2(__float2half_rn(x.z - __half2float(hz)),
                 __float2half_rn(x.w - __half2float(hw)));

    __half* d = dst + row * XEXT;
    *(uint2*)(d + c) = H;
    *(uint2*)(d + 1024 + c) = H;
    *(uint2*)(d + 2048 + c) = L;
}

// ---------------------------------------------------------------------------
// Merged Q/K/V projection: cp.async 3-stage, 128x256 tile, ldmatrix.
// grid (4, 32, 3)
// ---------------------------------------------------------------------------
__global__ __launch_bounds__(256, 1)
void gemm16qkv_k(const __half* __restrict__ Xe,
                 const float* __restrict__ bq, const float* __restrict__ bk,
                 const float* __restrict__ bv,
                 float* __restrict__ qaug, float* __restrict__ kaug,
                 __half* __restrict__ v16)
{
    extern __shared__ char smc[];

    const int tid  = threadIdx.x;
    const int wid  = tid >> 5;
    const int lane = tid & 31;
    const int g    = lane >> 2;
    const int tig  = lane & 3;
    const int wm   = wid >> 2;
    const int wn   = wid & 3;

    const int z  = blockIdx.z;
    const int m0 = blockIdx.y * 128;
    const int n0 = blockIdx.x * 256;

    const __half* Ag = Xe + (size_t)m0 * XEXT;
    const __half* Bg = g_W16[z] + (size_t)n0 * XEXT;
    const float* bias = (z == 0) ? bq : (z == 1) ? bk : bv;

    const uint32_t smb = smem_u32(smc);
    const uint32_t aAdr = smb + (wm * 64) * 80 + ALOFF(lane);
    const uint32_t bAdr = smb + APART + (wn * 64) * 80 + BLOFF(lane);

    const int lr = tid >> 2, lc16 = tid & 3;

    float acc[4][8][4];
#pragma unroll
    for (int mf = 0; mf < 4; mf++)
#pragma unroll
        for (int nf = 0; nf < 8; nf++)
#pragma unroll
            for (int j = 0; j < 4; j++) acc[mf][nf][j] = 0.f;

    const int NCH = XEXT / 32;   // 96
    auto issue = [&](int c) {
        if (c < NCH) {
            uint32_t sb = smb + (c % 3) * STG;
#pragma unroll
            for (int i = 0; i < 2; i++) {
                int r = lr + i * 64;
                cp16(sb + r * 80 + lc16 * 16,
                     Ag + (size_t)r * XEXT + c * 32 + lc16 * 8);
            }
#pragma unroll
            for (int i = 0; i < 4; i++) {
                int r = lr + i * 64;
                cp16(sb + APART + r * 80 + lc16 * 16,
                     Bg + (size_t)r * XEXT + c * 32 + lc16 * 8);
            }
        }
        CPCOMMIT();
    };

    issue(0);
    issue(1);

    for (int c = 0; c < NCH; c++) {
        CPWAIT1();
        __syncthreads();
        issue(c + 2);

        uint32_t aA = aAdr + (c % 3) * STG;
        uint32_t bA = bAdr + (c % 3) * STG;
#pragma unroll
        for (int st = 0; st < 2; st++) {
            int kb = st * 32;
            uint32_t bfr[8][2];
#pragma unroll
            for (int nf2 = 0; nf2 < 4; nf2++) {
                uint32_t r[4];
                ldmx4(r, bA + nf2 * (16 * 80) + kb);
                bfr[nf2 * 2][0] = r[0]; bfr[nf2 * 2][1] = r[1];
                bfr[nf2 * 2 + 1][0] = r[2]; bfr[nf2 * 2 + 1][1] = r[3];
            }
#pragma unroll
            for (int mf = 0; mf < 4; mf++) {
                uint32_t afr[4];
                ldmx4(afr, aA + mf * (16 * 80) + kb);
#pragma unroll
                for (int nf = 0; nf < 8; nf++)
                    mma_fp16(acc[mf][nf], afr, bfr[nf]);
            }
        }
    }

#pragma unroll
    for (int mf = 0; mf < 4; mf++) {
        int row0 = m0 + wm * 64 + mf * 16 + g;
#pragma unroll
        for (int nf = 0; nf < 8; nf++) {
            int n = n0 + wn * 64 + nf * 8 + tig * 2;
            float bx = bias[n], by = bias[n + 1];
#pragma unroll
            for (int hf = 0; hf < 2; hf++) {
                int m = row0 + hf * 8;
                float vx = acc[mf][nf][hf * 2] + bx;
                float vy = acc[mf][nf][hf * 2 + 1] + by;
                int bb = m >> 11, s = m & 2047;
                int hh = n >> 6,  d = n & 63;
                if (z < 2) {
                    float* aug = (z == 0) ? qaug : kaug;
                    *(float2*)(aug +
                        ((size_t)((bb * 16 + hh) * 2048 + s)) * AUGC + d) =
                        make_float2(vx, vy);
                } else {
                    __half* vp = v16
                        + ((size_t)(bb * 16 + hh) * 64 + d) * 2048 + s;
                    vp[0]    = __float2half_rn(vx);
                    vp[2048] = __float2half_rn(vy);
                }
            }
        }
    }
}

// ---------------------------------------------------------------------------
// Out projection: A = Oext [oh|oh] (K=2048), B = W16[3]+1024 = [Wh|Wl].
// grid (4, 32)
// ---------------------------------------------------------------------------
__global__ __launch_bounds__(256, 1)
void gemm16o_k(const __half* __restrict__ Ae, const float* __restrict__ bias,
               float* __restrict__ C)
{
    extern __shared__ char smc[];

    const int tid  = threadIdx.x;
    const int wid  = tid >> 5;
    const int lane = tid & 31;
    const int g    = lane >> 2;
    const int tig  = lane & 3;
    const int wm   = wid >> 2;
    const int wn   = wid & 3;

    const int m0 = blockIdx.y * 128;
    const int n0 = blockIdx.x * 256;

    const __half* Ag = Ae + (size_t)m0 * OEXT;
    const __half* Bg = g_W16[3] + 1024 + (size_t)n0 * XEXT;

    const uint32_t smb = smem_u32(smc);
    const uint32_t aAdr = smb + (wm * 64) * 80 + ALOFF(lane);
    const uint32_t bAdr = smb + APART + (wn * 64) * 80 + BLOFF(lane);

    const int lr = tid >> 2, lc16 = tid & 3;

    float acc[4][8][4];
#pragma unroll
    for (int mf = 0; mf < 4; mf++)
#pragma unroll
        for (int nf = 0; nf < 8; nf++)
#pragma unroll
            for (int j = 0; j < 4; j++) acc[mf][nf][j] = 0.f;

    const int NCH = OEXT / 32;   // 64
    auto issue = [&](int c) {
        if (c < NCH) {
            uint32_t sb = smb + (c % 3) * STG;
#pragma unroll
            for (int i = 0; i < 2; i++) {
                int r = lr + i * 64;
                cp16(sb + r * 80 + lc16 * 16,
                     Ag + (size_t)r * OEXT + c * 32 + lc16 * 8);
            }
#pragma unroll
            for (int i = 0; i < 4; i++) {
                int r = lr + i * 64;
                cp16(sb + APART + r * 80 + lc16 * 16,
                     Bg + (size_t)r * XEXT + c * 32 + lc16 * 8);
            }
        }
        CPCOMMIT();
    };

    issue(0);
    issue(1);

    for (int c = 0; c < NCH; c++) {
        CPWAIT1();
        __syncthreads();
        issue(c + 2);

        uint32_t aA = aAdr + (c % 3) * STG;
        uint32_t bA = bAdr + (c % 3) * STG;
#pragma unroll
        for (int st = 0; st < 2; st++) {
            int kb = st * 32;
            uint32_t bfr[8][2];
#pragma unroll
            for (int nf2 = 0; nf2 < 4; nf2++) {
                uint32_t r[4];
                ldmx4(r, bA + nf2 * (16 * 80) + kb);
                bfr[nf2 * 2][0] = r[0]; bfr[nf2 * 2][1] = r[1];
                bfr[nf2 * 2 + 1][0] = r[2]; bfr[nf2 * 2 + 1][1] = r[3];
            }
#pragma unroll
            for (int mf = 0; mf < 4; mf++) {
                uint32_t afr[4];
                ldmx4(afr, aA + mf * (16 * 80) + kb);
#pragma unroll
                for (int nf = 0; nf < 8; nf++)
                    mma_fp16(acc[mf][nf], afr, bfr[nf]);
            }
        }
    }

#pragma unroll
    for (int mf = 0; mf < 4; mf++) {
        int row0 = m0 + wm * 64 + mf * 16 + g;
#pragma unroll
        for (int nf = 0; nf < 8; nf++) {
            int n = n0 + wn * 64 + nf * 8 + tig * 2;
            float bx = bias[n], by = bias[n + 1];
#pragma unroll
            for (int hf = 0; hf < 2; hf++) {
                int m = row0 + hf * 8;
                *(float2*)(C + (size_t)m * Dd + n) =
                    make_float2(acc[mf][nf][hf * 2] + bx,
                                acc[mf][nf][hf * 2 + 1] + by);
            }
        }
    }
}

// ---------------------------------------------------------------------------
// FFT (known-good)
// ---------------------------------------------------------------------------
__global__ __launch_bounds__(256)
void fft_k(float* qaug, float* kaug, const float* twp, const float* fwp)
{
    __shared__ float  sr[2][2048];
    __shared__ float  si[2][2048];
    __shared__ float2 tw[1024];

    int bh     = blockIdx.x;
    int tensor = blockIdx.y;
    int dk0    = blockIdx.z * 2;
    float* base = (tensor == 0 ? qaug : kaug) + (size_t)bh * Ss * AUGC;
    int tid = threadIdx.x;

    for (int t = tid; t < 1024; t += 256) tw[t] = g_twid[t];

    for (int idx = tid; idx < 2 * Ss; idx += 256) {
        int l = idx & 1;
        int s = idx >> 1;
        float v = base[(size_t)s * AUGC + dk0 + l];
        int rs = __brev((unsigned)s) >> 21;
        sr[l][rs] = v;
        si[l][rs] = 0.f;
    }
    __syncthreads();

    for (int len = 2; len <= 2048; len <<= 1) {
        int half = len >> 1;
        int step = 2048 / len;
        for (int idx = tid; idx < 2048; idx += 256) {
            int l   = idx >> 10;
            int bix = idx & 1023;
            int grp = bix / half;
            int pos = bix - grp * half;
            int i0 = grp * len + pos;
            int i1 = i0 + half;
            float2 w = tw[pos * step];
            float xr = sr[l][i1], xi = si[l][i1];
            float tr = xr * w.x - xi * w.y;
            float ti = xr * w.y + xi * w.x;
            float ur = sr[l][i0], ui = si[l][i0];
            sr[l][i0] = ur + tr;  si[l][i0] = ui + ti;
            sr[l][i1] = ur - tr;  si[l][i1] = ui - ti;
        }
        __syncthreads();
    }

    float ft, ff;
    if (tensor == 0) { ft = twp[0] * 0.125f; ff = fwp[0] * 0.125f; }
    else             { ft = 1.f;             ff = 1.f; }

    for (int idx = tid; idx < 2 * Ss; idx += 256) {
        int l = idx & 1;
        int s = idx >> 1;
        size_t o = (size_t)s * AUGC + dk0 + l;
        if (tensor == 0) base[o] *= ft;
        base[o + 64]  = sr[l][s] * ff;
        base[o + 128] = si[l][s] * ff;
    }
}

// ---------------------------------------------------------------------------
template<int QMODE>
__global__ __launch_bounds__(256)
void convert16_k(const float* __restrict__ src, __half* __restrict__ dst)
{
    size_t i4 = (size_t)blockIdx.x * 256 + threadIdx.x;
    size_t row = i4 / 48;
    int c4 = (int)(i4 % 48);
    float4 x = ((const float4*)src)[i4];

    __half hx = __float2half_rn(x.x), hy = __float2half_rn(x.y);
    __half hz = __float2half_rn(x.z), hw = __float2half_rn(x.w);
    __half lx = __float2half_rn(x.x - __half2float(hx));
    __half ly = __float2half_rn(x.y - __half2float(hy));
    __half lz = __float2half_rn(x.z - __half2float(hz));
    __half lw = __float2half_rn(x.w - __half2float(hw));

    uint2 H, L;
    H.x = packh2(hx, hy); H.y = packh2(hz, hw);
    L.x = packh2(lx, ly); L.y = packh2(lz, lw);

    __half* drow = dst + row * ECOLS;
    int base, f, span;
    if (c4 < 16) { base = 0;   f = c4 * 4;      span = 64;  }
    else         { base = 192; f = c4 * 4 - 64; span = 128; }

    *(uint2*)(drow + base + f) = H;
    if (QMODE) {
        *(uint2*)(drow + base + span + f)     = L;
        *(uint2*)(drow + base + 2 * span + f) = H;
    } else {
        *(uint2*)(drow + base + span + f)     = H;
        *(uint2*)(drow + base + 2 * span + f) = L;
    }
}

// ---------------------------------------------------------------------------
// fp16 mma scores: cp.async 3-stage + ldmatrix, 128x256 tile (R12 geometry).
// EPI=0 (freq): grid (8, 9, 32); EPI=1 (time): grid (8, 16, 32).
// ---------------------------------------------------------------------------
template<int KOFF, int NCH, int EPI>
__global__ __launch_bounds__(256, 1)
void scores16_k(const __half* __restrict__ Qe, const __half* __restrict__ Ke,
                float* __restrict__ attn, float* __restrict__ Freq,
                float* __restrict__ pmax, float* __restrict__ psum)
{
    extern __shared__ char smc[];

    const int tid  = threadIdx.x;
    const int wid  = tid >> 5;
    const int lane = tid & 31;
    const int g    = lane >> 2;
    const int tig  = lane & 3;
    const int wm   = wid >> 2;
    const int wn   = wid & 3;

    const int ntile = blockIdx.x;
    const int mtile = blockIdx.y;
    const int bh    = blockIdx.z;
    const int m0 = mtile * 128;
    const int n0 = ntile * 256;

    const __half* Ag = Qe + ((size_t)bh * Ss + m0) * ECOLS + KOFF;
    const __half* Bg = Ke + ((size_t)bh * Ss + n0) * ECOLS + KOFF;

    const uint32_t smb = smem_u32(smc);
    const uint32_t aAdr = smb + (wm * 64) * 80 + ALOFF(lane);
    const uint32_t bAdr = smb + APART + (wn * 64) * 80 + BLOFF(lane);

    const int lr = tid >> 2, lc16 = tid & 3;

    float acc[4][8][4];
#pragma unroll
    for (int mf = 0; mf < 4; mf++)
#pragma unroll
        for (int nf = 0; nf < 8; nf++)
#pragma unroll
            for (int j = 0; j < 4; j++) acc[mf][nf][j] = 0.f;

    auto issue = [&](int c) {
        if (c < NCH) {
            uint32_t sb = smb + (c % 3) * STG;
#pragma unroll
            for (int i = 0; i < 2; i++) {
                int r = lr + i * 64;
                cp16(sb + r * 80 + lc16 * 16,
                     Ag + (size_t)r * ECOLS + c * 32 + lc16 * 8);
            }
#pragma unroll
            for (int i = 0; i < 4; i++) {
                int r = lr + i * 64;
                cp16(sb + APART + r * 80 + lc16 * 16,
                     Bg + (size_t)r * ECOLS + c * 32 + lc16 * 8);
            }
        }
        CPCOMMIT();
    };

    issue(0);
    issue(1);

    for (int c = 0; c < NCH; c++) {
        CPWAIT1();
        __syncthreads();
        issue(c + 2);

        uint32_t aA = aAdr + (c % 3) * STG;
        uint32_t bA = bAdr + (c % 3) * STG;
#pragma unroll
        for (int st = 0; st < 2; st++) {
            int kb = st * 32;
            uint32_t bfr[8][2];
#pragma unroll
            for (int nf2 = 0; nf2 < 4; nf2++) {
                uint32_t r[4];
                ldmx4(r, bA + nf2 * (16 * 80) + kb);
                bfr[nf2 * 2][0] = r[0]; bfr[nf2 * 2][1] = r[1];
                bfr[nf2 * 2 + 1][0] = r[2]; bfr[nf2 * 2 + 1][1] = r[3];
            }
#pragma unroll
            for (int mf = 0; mf < 4; mf++) {
                uint32_t afr[4];
                ldmx4(afr, aA + mf * (16 * 80) + kb);
#pragma unroll
                for (int nf = 0; nf < 8; nf++)
                    mma_fp16(acc[mf][nf], afr, bfr[nf]);
            }
        }
    }

    const int cbase = n0 + wn * 64 + tig * 2;

    if (EPI == 0) {
#pragma unroll
        for (int mf = 0; mf < 4; mf++) {
            int r0 = m0 + wm * 64 + mf * 16 + g;
#pragma unroll
            for (int hf = 0; hf < 2; hf++) {
                int r = r0 + hf * 8;
                if (r <= 1024) {
                    float* frow = Freq + ((size_t)bh * 1025 + r) * Ss;
#pragma unroll
                    for (int nf = 0; nf < 8; nf++)
                        *(float2*)(frow + cbase + nf * 8) =
                            make_float2(acc[mf][nf][hf * 2], acc[mf][nf][hf * 2 + 1]);
                }
            }
        }
    } else {
#pragma unroll
        for (int mf = 0; mf < 4; mf++) {
            int row0 = m0 + wm * 64 + mf * 16 + g;
#pragma unroll
            for (int hf = 0; hf < 2; hf++) {
                int r = row0 + hf * 8;
                if (r <= 1024) {
                    const float* fr = Freq + ((size_t)bh * 1025 + r) * Ss;
#pragma unroll
                    for (int nf = 0; nf < 8; nf++) {
                        float2 f = *(const float2*)(fr + cbase + nf * 8);
                        acc[mf][nf][hf * 2]     += f.x;
                        acc[mf][nf][hf * 2 + 1] += f.y;
                    }
                } else {
                    const float* fr = Freq + ((size_t)bh * 1025 + (2048 - r)) * Ss;
#pragma unroll
                    for (int nf = 0; nf < 8; nf++) {
                        int c0 = cbase + nf * 8;
                        acc[mf][nf][hf * 2]     += fr[(2048 - c0) & 2047];
                        acc[mf][nf][hf * 2 + 1] += fr[2047 - c0];
                    }
                }
            }

            float mx0 = -3.4e38f, mx1 = -3.4e38f;
#pragma unroll
            for (int nf = 0; nf < 8; nf++) {
                mx0 = fmaxf(mx0, fmaxf(acc[mf][nf][0], acc[mf][nf][1]));
                mx1 = fmaxf(mx1, fmaxf(acc[mf][nf][2], acc[mf][nf][3]));
            }
            mx0 = fmaxf(mx0, __shfl_xor_sync(0xffffffffu, mx0, 1));
            mx0 = fmaxf(mx0, __shfl_xor_sync(0xffffffffu, mx0, 2));
            mx1 = fmaxf(mx1, __shfl_xor_sync(0xffffffffu, mx1, 1));
            mx1 = fmaxf(mx1, __shfl_xor_sync(0xffffffffu, mx1, 2));

            float s0 = 0.f, s1 = 0.f;
#pragma unroll
            for (int nf = 0; nf < 8; nf++) {
                s0 += __expf(acc[mf][nf][0] - mx0) + __expf(acc[mf][nf][1] - mx0);
                s1 += __expf(acc[mf][nf][2] - mx1) + __expf(acc[mf][nf][3] - mx1);
            }
            s0 += __shfl_xor_sync(0xffffffffu, s0, 1);
            s0 += __shfl_xor_sync(0xffffffffu, s0, 2);
            s1 += __shfl_xor_sync(0xffffffffu, s1, 1);
            s1 += __shfl_xor_sync(0xffffffffu, s1, 2);

            if (tig == 0) {
                size_t gr0 = ((size_t)bh * Ss + row0) * NPART + ntile * 4 + wn;
                pmax[gr0] = mx0; psum[gr0] = s0;
                size_t gr1 = gr0 + 8 * NPART;
                pmax[gr1] = mx1; psum[gr1] = s1;
            }

            float* arow  = attn + ((size_t)bh << 22) + (size_t)row0 * Ss + cbase;
            float* arow8 = arow + 8 * Ss;
#pragma unroll
            for (int nf = 0; nf < 8; nf++)
                *(float2*)(arow + nf * 8) = make_float2(acc[mf][nf][0], acc[mf][nf][1]);
#pragma unroll
            for (int nf = 0; nf < 8; nf++)
                *(float2*)(arow8 + nf * 8) = make_float2(acc[mf][nf][2], acc[mf][nf][3]);
        }
    }
}

// ---------------------------------------------------------------------------
__global__ __launch_bounds__(256)
void combine_k(const float* __restrict__ pmax, const float* __restrict__ psum,
               float* __restrict__ rowm, float* __restrict__ rowz)
{
    int r = blockIdx.x * 256 + threadIdx.x;
    float m = -3.4e38f;
#pragma unroll
    for (int i = 0; i < NPART; i++) m = fmaxf(m, pmax[(size_t)r * NPART + i]);
    float z = 0.f;
#pragma unroll
    for (int i = 0; i < NPART; i++)
        z += psum[(size_t)r * NPART + i] * __expf(pmax[(size_t)r * NPART + i] - m);
    rowm[r] = m;
    rowz[r] = 1.f / z;
}

// ---------------------------------------------------------------------------
// Fused normalize + attn*V; epilogue emits O as [oh|oh] (K=2048 for outproj)
// ---------------------------------------------------------------------------
#define AVA (128 * 80)
#define AVB (64 * 80)

__global__ __launch_bounds__(256, 2)
void attnv16_k(float* __restrict__ attn, const __half* __restrict__ V16,
               const float* __restrict__ rowm, const float* __restrict__ rowz,
               __half* __restrict__ Oe)
{
    __shared__ char smc[2 * AVA + 2 * AVB];

    const int tid  = threadIdx.x;
    const int wid  = tid >> 5;
    const int lane = tid & 31;
    const int g    = lane >> 2;
    const int tig  = lane & 3;
    const int wm   = wid & 3;
    const int wn   = wid >> 2;

    const int mt = blockIdx.x, bh = blockIdx.y;
    const int m0 = mt * 128;
    float* Ab = attn + ((size_t)bh << 22) + (size_t)m0 * Ss;
    const __half* Vb = V16 + (size_t)bh * 64 * 2048;

    const int prow = tid >> 1;
    const int ph   = tid & 1;
    const float rm = rowm[bh * Ss + m0 + prow];
    const float rz = rowz[bh * Ss + m0 + prow];

    const int brow = tid >> 2;
    const int bq   = tid & 3;

    const uint32_t smb = smem_u32(smc);
    const uint32_t aAdr = smb + (wm * 32) * 80 + ALOFF(lane);
    const uint32_t bAdr = smb + 2 * AVA + (wn * 32) * 80 + BLOFF(lane);

    float acc[2][4][4];
#pragma unroll
    for (int mf = 0; mf < 2; mf++)
#pragma unroll
        for (int nf = 0; nf < 4; nf++)
#pragma unroll
            for (int j = 0; j < 4; j++) acc[mf][nf][j] = 0.f;

    float4 pa[4];
    uint4  vb;

    auto ldg = [&](int c) {
#pragma unroll
        for (int i = 0; i < 4; i++)
            pa[i] = *(const float4*)(Ab + (size_t)prow * Ss + c * 32 + ph * 16 + i * 4);
        vb = *(const uint4*)(Vb + (size_t)brow * 2048 + c * 32 + bq * 8);
    };
    auto sts = [&](int b, int c) {
        char* a16 = smc + b * AVA;
        float p[16];
#pragma unroll
        for (int i = 0; i < 4; i++) {
            p[4*i+0] = __expf(pa[i].x - rm) * rz;
            p[4*i+1] = __expf(pa[i].y - rm) * rz;
            p[4*i+2] = __expf(pa[i].z - rm) * rz;
            p[4*i+3] = __expf(pa[i].w - rm) * rz;
            *(float4*)(Ab + (size_t)prow * Ss + c * 32 + ph * 16 + i * 4) =
                make_float4(p[4*i+0], p[4*i+1], p[4*i+2], p[4*i+3]);
        }
        uint4 h0;
        h0.x = packh2(__float2half_rn(p[0]),  __float2half_rn(p[1]));
        h0.y = packh2(__float2half_rn(p[2]),  __float2half_rn(p[3]));
        h0.z = packh2(__float2half_rn(p[4]),  __float2half_rn(p[5]));
        h0.w = packh2(__float2half_rn(p[6]),  __float2half_rn(p[7]));
        uint4 h1;
        h1.x = packh2(__float2half_rn(p[8]),  __float2half_rn(p[9]));
        h1.y = packh2(__float2half_rn(p[10]), __float2half_rn(p[11]));
        h1.z = packh2(__float2half_rn(p[12]), __float2half_rn(p[13]));
        h1.w = packh2(__float2half_rn(p[14]), __float2half_rn(p[15]));
        char* arow = a16 + prow * 80 + ph * 32;
        *(uint4*)(arow)      = h0;
        *(uint4*)(arow + 16) = h1;
        char* b16 = smc + 2 * AVA + b * AVB;
        *(uint4*)(b16 + brow * 80 + bq * 16) = vb;
    };

    ldg(0);
    sts(0, 0);
    __syncthreads();

    const int NCH = 64;
    for (int c = 0; c < NCH; c++) {
        int buf = c & 1;
        if (c + 1 < NCH) ldg(c + 1);

        uint32_t aA = aAdr + buf * AVA;
        uint32_t bA = bAdr + buf * AVB;
#pragma unroll
        for (int st = 0; st < 2; st++) {
            int kb = st * 32;
            uint32_t bfr[4][2];
#pragma unroll
            for (int nf2 = 0; nf2 < 2; nf2++) {
                uint32_t r[4];
                ldmx4(r, bA + nf2 * (16 * 80) + kb);
                bfr[nf2 * 2][0] = r[0]; bfr[nf2 * 2][1] = r[1];
                bfr[nf2 * 2 + 1][0] = r[2]; bfr[nf2 * 2 + 1][1] = r[3];
            }
#pragma unroll
            for (int mf = 0; mf < 2; mf++) {
                uint32_t afr[4];
                ldmx4(afr, aA + mf * (16 * 80) + kb);
#pragma unroll
                for (int nf = 0; nf < 4; nf++)
                    mma_fp16(acc[mf][nf], afr, bfr[nf]);
            }
        }
        if (c + 1 < NCH) sts(buf ^ 1, c + 1);
        __syncthreads();
    }

    // epilogue: O -> [oh | oh], row = b*2048+s, col = h*64+dk
    size_t rowbase = (size_t)(bh >> 4) * Ss + m0;
    int colbase = (bh & 15) * 64;
#pragma unroll
    for (int mf = 0; mf < 2; mf++) {
        int r0 = wm * 32 + mf * 16 + g;
#pragma unroll
        for (int nf = 0; nf < 4; nf++) {
            int col = colbase + wn * 32 + nf * 8 + tig * 2;
#pragma unroll
            for (int hf = 0; hf < 2; hf++) {
                float vx = acc[mf][nf][hf * 2], vy = acc[mf][nf][hf * 2 + 1];
                uint32_t H = packh2(__float2half_rn(vx), __float2half_rn(vy));
                __half* orow = Oe + (rowbase + r0 + hf * 8) * OEXT;
                *(uint32_t*)(orow + col)        = H;
                *(uint32_t*)(orow + 1024 + col) = H;
            }
        }
    }
}

// ---------------------------------------------------------------------------
extern "C" void kernel_launch(void* const* d_in, const int* in_sizes, int n_in,
                              void* d_out, int out_size)
{
    const float* x  = (const float*)d_in[0];
    const float* Wq = (const float*)d_in[1];
    const float* bq = (const float*)d_in[2];
    const float* Wk = (const float*)d_in[3];
    const float* bk = (const float*)d_in[4];
    const float* Wv = (const float*)d_in[5];
    const float* bv = (const float*)d_in[6];
    const float* Wo = (const float*)d_in[7];
    const float* bo = (const float*)d_in[8];
    const float* tw = (const float*)d_in[9];
    const float* fw = (const float*)d_in[10];

    float* out  = (float*)d_out;
    float* attn = out + (size_t)Mm * Dd;

    float *qaug, *kaug, *freq, *pmax, *psum, *rowm, *rowz;
    __half *qe, *ke, *v16, *xe, *oe;
    cudaGetSymbolAddress((void**)&qaug, g_Qaug);
    cudaGetSymbolAddress((void**)&kaug, g_Kaug);
    cudaGetSymbolAddress((void**)&qe,   g_Qe16);
    cudaGetSymbolAddress((void**)&ke,   g_Ke16);
    cudaGetSymbolAddress((void**)&v16,  g_V16);
    cudaGetSymbolAddress((void**)&freq, g_Freq);
    cudaGetSymbolAddress((void**)&xe,   g_Xext);
    cudaGetSymbolAddress((void**)&oe,   g_Oext);
    cudaGetSymbolAddress((void**)&pmax, g_pmax);
    cudaGetSymbolAddress((void**)&psum, g_psum);
    cudaGetSymbolAddress((void**)&rowm, g_rowm);
    cudaGetSymbolAddress((void**)&rowz, g_rowz);

    cudaFuncSetAttribute(scores16_k<192, 12, 0>,
                         cudaFuncAttributeMaxDynamicSharedMemorySize, SMPIPE);
    cudaFuncSetAttribute(scores16_k<0, 6, 1>,
                         cudaFuncAttributeMaxDynamicSharedMemorySize, SMPIPE);
    cudaFuncSetAttribute(gemm16qkv_k, cudaFuncAttributeMaxDynamicSharedMemorySize, SMPIPE);
    cudaFuncSetAttribute(gemm16o_k,   cudaFuncAttributeMaxDynamicSharedMemorySize, SMPIPE);

    dim3 blk(256);

    twiddle_init_k<<<4, 256>>>();

    // ext conversions
    convx_k<<<Mm, 256>>>(x, xe);
    convw_k<<<dim3(Dd, 4), 256>>>(Wq, Wk, Wv, Wo);

    // merged Q/K/V projections
    gemm16qkv_k<<<dim3(4, 32, 3), blk, SMPIPE>>>(xe, bq, bk, bv, qaug, kaug, v16);

    // FFT
    fft_k<<<dim3(BHh, 2, 32), blk>>>(qaug, kaug, tw, fw);

    // fp16x2 split for scores
    {
        int nblk = (int)(((size_t)BHh * Ss * 48) / 256);
        convert16_k<1><<<nblk, 256>>>(qaug, qe);
        convert16_k<0><<<nblk, 256>>>(kaug, ke);
    }

    // freq scores rows 0..1024 -> staged (R12 structure)
    scores16_k<192, 12, 0><<<dim3(8, 9, BHh), blk, SMPIPE>>>(qe, ke, attn, freq, pmax, psum);

    // time scores + freq add + softmax partials
    scores16_k<0, 6, 1><<<dim3(8, 16, BHh), blk, SMPIPE>>>(qe, ke, attn, freq, pmax, psum);

    // combine partials
    combine_k<<<(BHh * Ss) / 256, 256>>>(pmax, psum, rowm, rowz);

    // fused normalize + attn*V -> O [oh|oh]
    attnv16_k<<<dim3(16, BHh), blk>>>(attn, v16, rowm, rowz, oe);

    // out projection (K=2048 over [Wh|Wl])
    gemm16o_k<<<dim3(4, 32), blk, SMPIPE>>>(oe, bo, out);
}

// round 16
// speedup vs baseline: 1.1058x; 1.0214x over previous
#include <cuda_runtime.h>
#include <cuda_fp16.h>
#include <math.h>
#include <stdint.h>

// Problem constants
#define Bb   2
#define Ss   2048
#define Dd   1024
#define Hh   16
#define DKk  64
#define AUGC 192
#define ECOLS 576
#define XEXT 3072
#define OEXT 2048             // O ext: [oh | oh]
#define BHh  (Bb * Hh)
#define Mm   (Bb * Ss)
#define NPART 32

// Scratch
__device__ float   g_Qaug[(size_t)BHh * Ss * AUGC];
__device__ float   g_Kaug[(size_t)BHh * Ss * AUGC];
__device__ __half  g_Qe16[(size_t)BHh * Ss * ECOLS];
__device__ __half  g_Ke16[(size_t)BHh * Ss * ECOLS];
__device__ __half  g_V16 [(size_t)BHh * DKk * Ss];
__device__ float   g_Freq[(size_t)BHh * 1025 * Ss];
__device__ __half  g_Stage[(size_t)BHh * Ss * Ss];   // fp16 (logit - mx_local)
__device__ __half  g_Xext[(size_t)Mm * XEXT];
__device__ __half  g_W16 [4][(size_t)Dd * XEXT];
__device__ __half  g_Oext[(size_t)Mm * OEXT];
__device__ float   g_pmax[(size_t)BHh * Ss * NPART];
__device__ float   g_psum[(size_t)BHh * Ss * NPART];
__device__ float   g_rowm[(size_t)BHh * Ss];
__device__ float   g_rowz[(size_t)BHh * Ss];
__device__ float2  g_twid[1024];

// ---------------------------------------------------------------------------
__device__ __forceinline__ uint32_t packh2(__half a, __half b) {
    __half2 p = __halves2half2(a, b);
    return *reinterpret_cast<uint32_t*>(&p);
}
__device__ __forceinline__ void mma_fp16(float c[4], const uint32_t a[4],
                                         const uint32_t b[2]) {
    asm volatile(
        "mma.sync.aligned.m16n8k16.row.col.f32.f16.f16.f32 "
        "{%0,%1,%2,%3}, {%4,%5,%6,%7}, {%8,%9}, {%0,%1,%2,%3};"
        : "+f"(c[0]), "+f"(c[1]), "+f"(c[2]), "+f"(c[3])
        : "r"(a[0]), "r"(a[1]), "r"(a[2]), "r"(a[3]), "r"(b[0]), "r"(b[1]));
}
__device__ __forceinline__ uint32_t smem_u32(const void* p) {
    uint32_t a;
    asm("{ .reg .u64 t; cvta.to.shared.u64 t, %1; cvt.u32.u64 %0, t; }"
        : "=r"(a) : "l"(p));
    return a;
}
__device__ __forceinline__ void ldmx4(uint32_t r[4], uint32_t addr) {
    asm volatile("ldmatrix.sync.aligned.m8n8.x4.shared.b16 {%0,%1,%2,%3}, [%4];"
        : "=r"(r[0]), "=r"(r[1]), "=r"(r[2]), "=r"(r[3]) : "r"(addr));
}
__device__ __forceinline__ void cp16(uint32_t sm, const void* g) {
    asm volatile("cp.async.ca.shared.global [%0], [%1], 16;"
                 :: "r"(sm), "l"(g) : "memory");
}
#define CPCOMMIT() asm volatile("cp.async.commit_group;" ::: "memory")
#define CPWAIT1()  asm volatile("cp.async.wait_group 1;" ::: "memory")

#define ALOFF(lane) (((lane) & 15) * 80 + (((lane) >> 4) & 1) * 16)
#define BLOFF(lane) (((((lane) >> 4) & 1) * 8 + ((lane) & 7)) * 80 + (((lane) >> 3) & 1) * 16)

#define APART 10240
#define STG   30720
#define SMPIPE (3 * STG)   // 92160

// ---------------------------------------------------------------------------
__global__ void twiddle_init_k() {
    int t = blockIdx.x * blockDim.x + threadIdx.x;
    if (t < 1024) {
        double ang = -2.0 * 3.14159265358979323846 * (double)t / 2048.0;
        double s, c;
        sincos(ang, &s, &c);
        g_twid[t] = make_float2((float)c, (float)s);
    }
}

// ---------------------------------------------------------------------------
__global__ __launch_bounds__(256)
void convx_k(const float* __restrict__ src, __half* __restrict__ dst)
{
    size_t i4 = (size_t)blockIdx.x * 256 + threadIdx.x;
    size_t row = i4 >> 8;
    int c = (int)(i4 & 255) * 4;
    float4 x = ((const float4*)src)[i4];

    __half hx = __float2half_rn(x.x), hy = __float2half_rn(x.y);
    __half hz = __float2half_rn(x.z), hw = __float2half_rn(x.w);
    uint2 H, L;
    H.x = packh2(hx, hy); H.y = packh2(hz, hw);
    L.x = packh2(__float2half_rn(x.x - __half2float(hx)),
                 __float2half_rn(x.y - __half2float(hy)));
    L.y = packh2(__float2half_rn(x.z - __half2float(hz)),
                 __float2half_rn(x.w - __half2float(hw)));

    __half* d = dst + row * XEXT;
    *(uint2*)(d + c) = H;
    *(uint2*)(d + 1024 + c) = L;
    *(uint2*)(d + 2048 + c) = H;
}

__global__ __launch_bounds__(256)
void convw_k(const float* __restrict__ Wq, const float* __restrict__ Wk,
             const float* __restrict__ Wv, const float* __restrict__ Wo)
{
    int z = blockIdx.y;
    const float* src = (z == 0) ? Wq : (z == 1) ? Wk : (z == 2) ? Wv : Wo;
    __half* dst = g_W16[z];

    size_t i4 = (size_t)blockIdx.x * 256 + threadIdx.x;
    size_t row = i4 >> 8;
    int c = (int)(i4 & 255) * 4;
    float4 x = ((const float4*)src)[i4];

    __half hx = __float2half_rn(x.x), hy = __float2half_rn(x.y);
    __half hz = __float2half_rn(x.z), hw = __float2half_rn(x.w);
    uint2 H, L;
    H.x = packh2(hx, hy); H.y = packh2(hz, hw);
    L.x = packh2(__float2half_rn(x.x - __half2float(hx)),
                 __float2half_rn(x.y - __half2float(hy)));
    L.y = packh2(__float2half_rn(x.z - __half2float(hz)),
                 __float2half_rn(x.w - __half2float(hw)));

    __half* d = dst + row * XEXT;
    *(uint2*)(d + c) = H;
    *(uint2*)(d + 1024 + c) = H;
    *(uint2*)(d + 2048 + c) = L;
}

// ---------------------------------------------------------------------------
// Merged Q/K/V projection: cp.async 3-stage, 128x256 tile, ldmatrix.
// ---------------------------------------------------------------------------
__global__ __launch_bounds__(256, 1)
void gemm16qkv_k(const __half* __restrict__ Xe,
                 const float* __restrict__ bq, const float* __restrict__ bk,
                 const float* __restrict__ bv,
                 float* __restrict__ qaug, float* __restrict__ kaug,
                 __half* __restrict__ v16)
{
    extern __shared__ char smc[];

    const int tid  = threadIdx.x;
    const int wid  = tid >> 5;
    const int lane = tid & 31;
    const int g    = lane >> 2;
    const int tig  = lane & 3;
    const int wm   = wid >> 2;
    const int wn   = wid & 3;

    const int z  = blockIdx.z;
    const int m0 = blockIdx.y * 128;
    const int n0 = blockIdx.x * 256;

    const __half* Ag = Xe + (size_t)m0 * XEXT;
    const __half* Bg = g_W16[z] + (size_t)n0 * XEXT;
    const float* bias = (z == 0) ? bq : (z == 1) ? bk : bv;

    const uint32_t smb = smem_u32(smc);
    const uint32_t aAdr = smb + (wm * 64) * 80 + ALOFF(lane);
    const uint32_t bAdr = smb + APART + (wn * 64) * 80 + BLOFF(lane);

    const int lr = tid >> 2, lc16 = tid & 3;

    float acc[4][8][4];
#pragma unroll
    for (int mf = 0; mf < 4; mf++)
#pragma unroll
        for (int nf = 0; nf < 8; nf++)
#pragma unroll
            for (int j = 0; j < 4; j++) acc[mf][nf][j] = 0.f;

    const int NCH = XEXT / 32;
    auto issue = [&](int c) {
        if (c < NCH) {
            uint32_t sb = smb + (c % 3) * STG;
#pragma unroll
            for (int i = 0; i < 2; i++) {
                int r = lr + i * 64;
                cp16(sb + r * 80 + lc16 * 16,
                     Ag + (size_t)r * XEXT + c * 32 + lc16 * 8);
            }
#pragma unroll
            for (int i = 0; i < 4; i++) {
                int r = lr + i * 64;
                cp16(sb + APART + r * 80 + lc16 * 16,
                     Bg + (size_t)r * XEXT + c * 32 + lc16 * 8);
            }
        }
        CPCOMMIT();
    };

    issue(0);
    issue(1);

    for (int c = 0; c < NCH; c++) {
        CPWAIT1();
        __syncthreads();
        issue(c + 2);

        uint32_t aA = aAdr + (c % 3) * STG;
        uint32_t bA = bAdr + (c % 3) * STG;
#pragma unroll
        for (int st = 0; st < 2; st++) {
            int kb = st * 32;
            uint32_t bfr[8][2];
#pragma unroll
            for (int nf2 = 0; nf2 < 4; nf2++) {
                uint32_t r[4];
                ldmx4(r, bA + nf2 * (16 * 80) + kb);
                bfr[nf2 * 2][0] = r[0]; bfr[nf2 * 2][1] = r[1];
                bfr[nf2 * 2 + 1][0] = r[2]; bfr[nf2 * 2 + 1][1] = r[3];
            }
#pragma unroll
            for (int mf = 0; mf < 4; mf++) {
                uint32_t afr[4];
                ldmx4(afr, aA + mf * (16 * 80) + kb);
#pragma unroll
                for (int nf = 0; nf < 8; nf++)
                    mma_fp16(acc[mf][nf], afr, bfr[nf]);
            }
        }
    }

#pragma unroll
    for (int mf = 0; mf < 4; mf++) {
        int row0 = m0 + wm * 64 + mf * 16 + g;
#pragma unroll
        for (int nf = 0; nf < 8; nf++) {
            int n = n0 + wn * 64 + nf * 8 + tig * 2;
            float bx = bias[n], by = bias[n + 1];
#pragma unroll
            for (int hf = 0; hf < 2; hf++) {
                int m = row0 + hf * 8;
                float vx = acc[mf][nf][hf * 2] + bx;
                float vy = acc[mf][nf][hf * 2 + 1] + by;
                int bb = m >> 11, s = m & 2047;
                int hh = n >> 6,  d = n & 63;
                if (z < 2) {
                    float* aug = (z == 0) ? qaug : kaug;
                    *(float2*)(aug +
                        ((size_t)((bb * 16 + hh) * 2048 + s)) * AUGC + d) =
                        make_float2(vx, vy);
                } else {
                    __half* vp = v16
                        + ((size_t)(bb * 16 + hh) * 64 + d) * 2048 + s;
                    vp[0]    = __float2half_rn(vx);
                    vp[2048] = __float2half_rn(vy);
                }
            }
        }
    }
}

// ---------------------------------------------------------------------------
// Out projection: A = Oext [oh|oh] (K=2048), B = W16[3]+1024 = [Wh|Wl].
// ---------------------------------------------------------------------------
__global__ __launch_bounds__(256, 1)
void gemm16o_k(const __half* __restrict__ Ae, const float* __restrict__ bias,
               float* __restrict__ C)
{
    extern __shared__ char smc[];

    const int tid  = threadIdx.x;
    const int wid  = tid >> 5;
    const int lane = tid & 31;
    const int g    = lane >> 2;
    const int tig  = lane & 3;
    const int wm   = wid >> 2;
    const int wn   = wid & 3;

    const int m0 = blockIdx.y * 128;
    const int n0 = blockIdx.x * 256;

    const __half* Ag = Ae + (size_t)m0 * OEXT;
    const __half* Bg = g_W16[3] + 1024 + (size_t)n0 * XEXT;

    const uint32_t smb = smem_u32(smc);
    const uint32_t aAdr = smb + (wm * 64) * 80 + ALOFF(lane);
    const uint32_t bAdr = smb + APART + (wn * 64) * 80 + BLOFF(lane);

    const int lr = tid >> 2, lc16 = tid & 3;

    float acc[4][8][4];
#pragma unroll
    for (int mf = 0; mf < 4; mf++)
#pragma unroll
        for (int nf = 0; nf < 8; nf++)
#pragma unroll
            for (int j = 0; j < 4; j++) acc[mf][nf][j] = 0.f;

    const int NCH = OEXT / 32;
    auto issue = [&](int c) {
        if (c < NCH) {
            uint32_t sb = smb + (c % 3) * STG;
#pragma unroll
            for (int i = 0; i < 2; i++) {
                int r = lr + i * 64;
                cp16(sb + r * 80 + lc16 * 16,
                     Ag + (size_t)r * OEXT + c * 32 + lc16 * 8);
            }
#pragma unroll
            for (int i = 0; i < 4; i++) {
                int r = lr + i * 64;
                cp16(sb + APART + r * 80 + lc16 * 16,
                     Bg + (size_t)r * XEXT + c * 32 + lc16 * 8);
            }
        }
        CPCOMMIT();
    };

    issue(0);
    issue(1);

    for (int c = 0; c < NCH; c++) {
        CPWAIT1();
        __syncthreads();
        issue(c + 2);

        uint32_t aA = aAdr + (c % 3) * STG;
        uint32_t bA = bAdr + (c % 3) * STG;
#pragma unroll
        for (int st = 0; st < 2; st++) {
            int kb = st * 32;
            uint32_t bfr[8][2];
#pragma unroll
            for (int nf2 = 0; nf2 < 4; nf2++) {
                uint32_t r[4];
                ldmx4(r, bA + nf2 * (16 * 80) + kb);
                bfr[nf2 * 2][0] = r[0]; bfr[nf2 * 2][1] = r[1];
                bfr[nf2 * 2 + 1][0] = r[2]; bfr[nf2 * 2 + 1][1] = r[3];
            }
#pragma unroll
            for (int mf = 0; mf < 4; mf++) {
                uint32_t afr[4];
                ldmx4(afr, aA + mf * (16 * 80) + kb);
#pragma unroll
                for (int nf = 0; nf < 8; nf++)
                    mma_fp16(acc[mf][nf], afr, bfr[nf]);
            }
        }
    }

#pragma unroll
    for (int mf = 0; mf < 4; mf++) {
        int row0 = m0 + wm * 64 + mf * 16 + g;
#pragma unroll
        for (int nf = 0; nf < 8; nf++) {
            int n = n0 + wn * 64 + nf * 8 + tig * 2;
            float bx = bias[n], by = bias[n + 1];
#pragma unroll
            for (int hf = 0; hf < 2; hf++) {
                int m = row0 + hf * 8;
                *(float2*)(C + (size_t)m * Dd + n) =
                    make_float2(acc[mf][nf][hf * 2] + bx,
                                acc[mf][nf][hf * 2 + 1] + by);
            }
        }
    }
}

// ---------------------------------------------------------------------------
// FFT (known-good)
// ---------------------------------------------------------------------------
__global__ __launch_bounds__(256)
void fft_k(float* qaug, float* kaug, const float* twp, const float* fwp)
{
    __shared__ float  sr[2][2048];
    __shared__ float  si[2][2048];
    __shared__ float2 tw[1024];

    int bh     = blockIdx.x;
    int tensor = blockIdx.y;
    int dk0    = blockIdx.z * 2;
    float* base = (tensor == 0 ? qaug : kaug) + (size_t)bh * Ss * AUGC;
    int tid = threadIdx.x;

    for (int t = tid; t < 1024; t += 256) tw[t] = g_twid[t];

    for (int idx = tid; idx < 2 * Ss; idx += 256) {
        int l = idx & 1;
        int s = idx >> 1;
        float v = base[(size_t)s * AUGC + dk0 + l];
        int rs = __brev((unsigned)s) >> 21;
        sr[l][rs] = v;
        si[l][rs] = 0.f;
    }
    __syncthreads();

    for (int len = 2; len <= 2048; len <<= 1) {
        int half = len >> 1;
        int step = 2048 / len;
        for (int idx = tid; idx < 2048; idx += 256) {
            int l   = idx >> 10;
            int bix = idx & 1023;
            int grp = bix / half;
            int pos = bix - grp * half;
            int i0 = grp * len + pos;
            int i1 = i0 + half;
            float2 w = tw[pos * step];
            float xr = sr[l][i1], xi = si[l][i1];
            float tr = xr * w.x - xi * w.y;
            float ti = xr * w.y + xi * w.x;
            float ur = sr[l][i0], ui = si[l][i0];
            sr[l][i0] = ur + tr;  si[l][i0] = ui + ti;
            sr[l][i1] = ur - tr;  si[l][i1] = ui - ti;
        }
        __syncthreads();
    }

    float ft, ff;
    if (tensor == 0) { ft = twp[0] * 0.125f; ff = fwp[0] * 0.125f; }
    else             { ft = 1.f;             ff = 1.f; }

    for (int idx = tid; idx < 2 * Ss; idx += 256) {
        int l = idx & 1;
        int s = idx >> 1;
        size_t o = (size_t)s * AUGC + dk0 + l;
        if (tensor == 0) base[o] *= ft;
        base[o + 64]  = sr[l][s] * ff;
        base[o + 128] = si[l][s] * ff;
    }
}

// ---------------------------------------------------------------------------
template<int QMODE>
__global__ __launch_bounds__(256)
void convert16_k(const float* __restrict__ src, __half* __restrict__ dst)
{
    size_t i4 = (size_t)blockIdx.x * 256 + threadIdx.x;
    size_t row = i4 / 48;
    int c4 = (int)(i4 % 48);
    float4 x = ((const float4*)src)[i4];

    __half hx = __float2half_rn(x.x), hy = __float2half_rn(x.y);
    __half hz = __float2half_rn(x.z), hw = __float2half_rn(x.w);
    __half lx = __float2half_rn(x.x - __half2float(hx));
    __half ly = __float2half_rn(x.y - __half2float(hy));
    __half lz = __float2half_rn(x.z - __half2float(hz));
    __half lw = __float2half_rn(x.w - __half2float(hw));

    uint2 H, L;
    H.x = packh2(hx, hy); H.y = packh2(hz, hw);
    L.x = packh2(lx, ly); L.y = packh2(lz, lw);

    __half* drow = dst + row * ECOLS;
    int base, f, span;
    if (c4 < 16) { base = 0;   f = c4 * 4;      span = 64;  }
    else         { base = 192; f = c4 * 4 - 64; span = 128; }

    *(uint2*)(drow + base + f) = H;
    if (QMODE) {
        *(uint2*)(drow + base + span + f)     = L;
        *(uint2*)(drow + base + 2 * span + f) = H;
    } else {
        *(uint2*)(drow + base + span + f)     = H;
        *(uint2*)(drow + base + 2 * span + f) = L;
    }
}

// ---------------------------------------------------------------------------
// fp16 mma scores. EPI=0 (freq): stage fp32 rows<=1024.
// EPI=1 (time): adds freq, stores fp16 (logit - mx_local) into Stage + partials.
// ---------------------------------------------------------------------------
template<int KOFF, int NCH, int EPI>
__global__ __launch_bounds__(256, 1)
void scores16_k(const __half* __restrict__ Qe, const __half* __restrict__ Ke,
                __half* __restrict__ Stage, float* __restrict__ Freq,
                float* __restrict__ pmax, float* __restrict__ psum)
{
    extern __shared__ char smc[];

    const int tid  = threadIdx.x;
    const int wid  = tid >> 5;
    const int lane = tid & 31;
    const int g    = lane >> 2;
    const int tig  = lane & 3;
    const int wm   = wid >> 2;
    const int wn   = wid & 3;

    const int ntile = blockIdx.x;
    const int mtile = blockIdx.y;
    const int bh    = blockIdx.z;
    const int m0 = mtile * 128;
    const int n0 = ntile * 256;

    const __half* Ag = Qe + ((size_t)bh * Ss + m0) * ECOLS + KOFF;
    const __half* Bg = Ke + ((size_t)bh * Ss + n0) * ECOLS + KOFF;

    const uint32_t smb = smem_u32(smc);
    const uint32_t aAdr = smb + (wm * 64) * 80 + ALOFF(lane);
    const uint32_t bAdr = smb + APART + (wn * 64) * 80 + BLOFF(lane);

    const int lr = tid >> 2, lc16 = tid & 3;

    float acc[4][8][4];
#pragma unroll
    for (int mf = 0; mf < 4; mf++)
#pragma unroll
        for (int nf = 0; nf < 8; nf++)
#pragma unroll
            for (int j = 0; j < 4; j++) acc[mf][nf][j] = 0.f;

    auto issue = [&](int c) {
        if (c < NCH) {
            uint32_t sb = smb + (c % 3) * STG;
#pragma unroll
            for (int i = 0; i < 2; i++) {
                int r = lr + i * 64;
                cp16(sb + r * 80 + lc16 * 16,
                     Ag + (size_t)r * ECOLS + c * 32 + lc16 * 8);
            }
#pragma unroll
            for (int i = 0; i < 4; i++) {
                int r = lr + i * 64;
                cp16(sb + APART + r * 80 + lc16 * 16,
                     Bg + (size_t)r * ECOLS + c * 32 + lc16 * 8);
            }
        }
        CPCOMMIT();
    };

    issue(0);
    issue(1);

    for (int c = 0; c < NCH; c++) {
        CPWAIT1();
        __syncthreads();
        issue(c + 2);

        uint32_t aA = aAdr + (c % 3) * STG;
        uint32_t bA = bAdr + (c % 3) * STG;
#pragma unroll
        for (int st = 0; st < 2; st++) {
            int kb = st * 32;
            uint32_t bfr[8][2];
#pragma unroll
            for (int nf2 = 0; nf2 < 4; nf2++) {
                uint32_t r[4];
                ldmx4(r, bA + nf2 * (16 * 80) + kb);
                bfr[nf2 * 2][0] = r[0]; bfr[nf2 * 2][1] = r[1];
                bfr[nf2 * 2 + 1][0] = r[2]; bfr[nf2 * 2 + 1][1] = r[3];
            }
#pragma unroll
            for (int mf = 0; mf < 4; mf++) {
                uint32_t afr[4];
                ldmx4(afr, aA + mf * (16 * 80) + kb);
#pragma unroll
                for (int nf = 0; nf < 8; nf++)
                    mma_fp16(acc[mf][nf], afr, bfr[nf]);
            }
        }
    }

    const int cbase = n0 + wn * 64 + tig * 2;

    if (EPI == 0) {
#pragma unroll
        for (int mf = 0; mf < 4; mf++) {
            int r0 = m0 + wm * 64 + mf * 16 + g;
#pragma unroll
            for (int hf = 0; hf < 2; hf++) {
                int r = r0 + hf * 8;
                if (r <= 1024) {
                    float* frow = Freq + ((size_t)bh * 1025 + r) * Ss;
#pragma unroll
                    for (int nf = 0; nf < 8; nf++)
                        *(float2*)(frow + cbase + nf * 8) =
                            make_float2(acc[mf][nf][hf * 2], acc[mf][nf][hf * 2 + 1]);
                }
            }
        }
    } else {
#pragma unroll
        for (int mf = 0; mf < 4; mf++) {
            int row0 = m0 + wm * 64 + mf * 16 + g;
#pragma unroll
            for (int hf = 0; hf < 2; hf++) {
                int r = row0 + hf * 8;
                if (r <= 1024) {
                    const float* fr = Freq + ((size_t)bh * 1025 + r) * Ss;
#pragma unroll
                    for (int nf = 0; nf < 8; nf++) {
                        float2 f = *(const float2*)(fr + cbase + nf * 8);
                        acc[mf][nf][hf * 2]     += f.x;
                        acc[mf][nf][hf * 2 + 1] += f.y;
                    }
                } else {
                    const float* fr = Freq + ((size_t)bh * 1025 + (2048 - r)) * Ss;
#pragma unroll
                    for (int nf = 0; nf < 8; nf++) {
                        int c0 = cbase + nf * 8;
                        acc[mf][nf][hf * 2]     += fr[(2048 - c0) & 2047];
                        acc[mf][nf][hf * 2 + 1] += fr[2047 - c0];
                    }
                }
            }

            float mx0 = -3.4e38f, mx1 = -3.4e38f;
#pragma unroll
            for (int nf = 0; nf < 8; nf++) {
                mx0 = fmaxf(mx0, fmaxf(acc[mf][nf][0], acc[mf][nf][1]));
                mx1 = fmaxf(mx1, fmaxf(acc[mf][nf][2], acc[mf][nf][3]));
            }
            mx0 = fmaxf(mx0, __shfl_xor_sync(0xffffffffu, mx0, 1));
            mx0 = fmaxf(mx0, __shfl_xor_sync(0xffffffffu, mx0, 2));
            mx1 = fmaxf(mx1, __shfl_xor_sync(0xffffffffu, mx1, 1));
            mx1 = fmaxf(mx1, __shfl_xor_sync(0xffffffffu, mx1, 2));

            float s0 = 0.f, s1 = 0.f;
#pragma unroll
            for (int nf = 0; nf < 8; nf++) {
                s0 += __expf(acc[mf][nf][0] - mx0) + __expf(acc[mf][nf][1] - mx0);
                s1 += __expf(acc[mf][nf][2] - mx1) + __expf(acc[mf][nf][3] - mx1);
            }
            s0 += __shfl_xor_sync(0xffffffffu, s0, 1);
            s0 += __shfl_xor_sync(0xffffffffu, s0, 2);
            s1 += __shfl_xor_sync(0xffffffffu, s1, 1);
            s1 += __shfl_xor_sync(0xffffffffu, s1, 2);

            if (tig == 0) {
                size_t gr0 = ((size_t)bh * Ss + row0) * NPART + ntile * 4 + wn;
                pmax[gr0] = mx0; psum[gr0] = s0;
                size_t gr1 = gr0 + 8 * NPART;
                pmax[gr1] = mx1; psum[gr1] = s1;
            }

            // store fp16 deltas (logit - mx_local), mx_local = pmax slot value
            __half* srow  = Stage + ((size_t)bh << 22) + (size_t)row0 * Ss + cbase;
            __half* srow8 = srow + 8 * Ss;
#pragma unroll
            for (int nf = 0; nf < 8; nf++)
                *(uint32_t*)(srow + nf * 8) =
                    packh2(__float2half_rn(acc[mf][nf][0] - mx0),
                           __float2half_rn(acc[mf][nf][1] - mx0));
#pragma unroll
            for (int nf = 0; nf < 8; nf++)
                *(uint32_t*)(srow8 + nf * 8) =
                    packh2(__float2half_rn(acc[mf][nf][2] - mx1),
                           __float2half_rn(acc[mf][nf][3] - mx1));
        }
    }
}

// ---------------------------------------------------------------------------
__global__ __launch_bounds__(256)
void combine_k(const float* __restrict__ pmax, const float* __restrict__ psum,
               float* __restrict__ rowm, float* __restrict__ rowz)
{
    int r = blockIdx.x * 256 + threadIdx.x;
    float m = -3.4e38f;
#pragma unroll
    for (int i = 0; i < NPART; i++) m = fmaxf(m, pmax[(size_t)r * NPART + i]);
    float z = 0.f;
#pragma unroll
    for (int i = 0; i < NPART; i++)
        z += psum[(size_t)r * NPART + i] * __expf(pmax[(size_t)r * NPART + i] - m);
    rowm[r] = m;
    rowz[r] = 1.f / z;
}

// ---------------------------------------------------------------------------
// Fused normalize + attn*V: reads fp16 staged deltas, reconstructs p with
// per-block mx_local from pmax, writes fp32 normalized attn, computes O.
// ---------------------------------------------------------------------------
#define AVA (128 * 80)
#define AVB (64 * 80)

__global__ __launch_bounds__(256, 2)
void attnv16_k(const __half* __restrict__ Stage, float* __restrict__ attn,
               const __half* __restrict__ V16,
               const float* __restrict__ rowm, const float* __restrict__ rowz,
               const float* __restrict__ pmax, __half* __restrict__ Oe)
{
    __shared__ char smc[2 * AVA + 2 * AVB];

    const int tid  = threadIdx.x;
    const int wid  = tid >> 5;
    const int lane = tid & 31;
    const int g    = lane >> 2;
    const int tig  = lane & 3;
    const int wm   = wid & 3;
    const int wn   = wid >> 2;

    const int mt = blockIdx.x, bh = blockIdx.y;
    const int m0 = mt * 128;
    const __half* Sb = Stage + ((size_t)bh << 22) + (size_t)m0 * Ss;
    float* Ab = attn + ((size_t)bh << 22) + (size_t)m0 * Ss;
    const __half* Vb = V16 + (size_t)bh * 64 * 2048;

    const int prow = tid >> 1;
    const int ph   = tid & 1;
    const float rm = rowm[bh * Ss + m0 + prow];
    const float rz = rowz[bh * Ss + m0 + prow];
    const float* pmrow = pmax + ((size_t)bh * Ss + m0 + prow) * NPART;

    const int brow = tid >> 2;
    const int bq   = tid & 3;

    const uint32_t smb = smem_u32(smc);
    const uint32_t aAdr = smb + (wm * 32) * 80 + ALOFF(lane);
    const uint32_t bAdr = smb + 2 * AVA + (wn * 32) * 80 + BLOFF(lane);

    float acc[2][4][4];
#pragma unroll
    for (int mf = 0; mf < 2; mf++)
#pragma unroll
        for (int nf = 0; nf < 4; nf++)
#pragma unroll
            for (int j = 0; j < 4; j++) acc[mf][nf][j] = 0.f;

    uint4  sv[2];     // 16 halfs (staged deltas)
    uint4  vb;
    float  mloc;

    auto ldg = [&](int c) {
        const __half* sp = Sb + (size_t)prow * Ss + c * 32 + ph * 16;
        sv[0] = *(const uint4*)(sp);
        sv[1] = *(const uint4*)(sp + 8);
        vb = *(const uint4*)(Vb + (size_t)brow * 2048 + c * 32 + bq * 8);
        mloc = pmrow[(c * 32 + ph * 16) >> 6];
    };
    auto sts = [&](int b, int c) {
        char* a16 = smc + b * AVA;
        float dm = rm - mloc;
        const __half2* h2 = (const __half2*)sv;
        float p[16];
#pragma unroll
        for (int j = 0; j < 8; j++) {
            float2 f = __half22float2(h2[j]);
            p[2 * j]     = __expf(f.x - dm) * rz;
            p[2 * j + 1] = __expf(f.y - dm) * rz;
        }
        // write normalized attn (fp32, checked output)
        float* aout = Ab + (size_t)prow * Ss + c * 32 + ph * 16;
#pragma unroll
        for (int i = 0; i < 4; i++)
            *(float4*)(aout + i * 4) =
                make_float4(p[4*i], p[4*i+1], p[4*i+2], p[4*i+3]);

        uint4 h0;
        h0.x = packh2(__float2half_rn(p[0]),  __float2half_rn(p[1]));
        h0.y = packh2(__float2half_rn(p[2]),  __float2half_rn(p[3]));
        h0.z = packh2(__float2half_rn(p[4]),  __float2half_rn(p[5]));
        h0.w = packh2(__float2half_rn(p[6]),  __float2half_rn(p[7]));
        uint4 h1;
        h1.x = packh2(__float2half_rn(p[8]),  __float2half_rn(p[9]));
        h1.y = packh2(__float2half_rn(p[10]), __float2half_rn(p[11]));
        h1.z = packh2(__float2half_rn(p[12]), __float2half_rn(p[13]));
        h1.w = packh2(__float2half_rn(p[14]), __float2half_rn(p[15]));
        char* arow = a16 + prow * 80 + ph * 32;
        *(uint4*)(arow)      = h0;
        *(uint4*)(arow + 16) = h1;
        char* b16 = smc + 2 * AVA + b * AVB;
        *(uint4*)(b16 + brow * 80 + bq * 16) = vb;
    };

    ldg(0);
    sts(0, 0);
    __syncthreads();

    const int NCH = 64;
    for (int c = 0; c < NCH; c++) {
        int buf = c & 1;
        if (c + 1 < NCH) ldg(c + 1);

        uint32_t aA = aAdr + buf * AVA;
        uint32_t bA = bAdr + buf * AVB;
#pragma unroll
        for (int st = 0; st < 2; st++) {
            int kb = st * 32;
            uint32_t bfr[4][2];
#pragma unroll
            for (int nf2 = 0; nf2 < 2; nf2++) {
                uint32_t r[4];
                ldmx4(r, bA + nf2 * (16 * 80) + kb);
                bfr[nf2 * 2][0] = r[0]; bfr[nf2 * 2][1] = r[1];
                bfr[nf2 * 2 + 1][0] = r[2]; bfr[nf2 * 2 + 1][1] = r[3];
            }
#pragma unroll
            for (int mf = 0; mf < 2; mf++) {
                uint32_t afr[4];
                ldmx4(afr, aA + mf * (16 * 80) + kb);
#pragma unroll
                for (int nf = 0; nf < 4; nf++)
                    mma_fp16(acc[mf][nf], afr, bfr[nf]);
            }
        }
        if (c + 1 < NCH) sts(buf ^ 1, c + 1);
        __syncthreads();
    }

    // epilogue: O -> [oh | oh]
    size_t rowbase = (size_t)(bh >> 4) * Ss + m0;
    int colbase = (bh & 15) * 64;
#pragma unroll
    for (int mf = 0; mf < 2; mf++) {
        int r0 = wm * 32 + mf * 16 + g;
#pragma unroll
        for (int nf = 0; nf < 4; nf++) {
            int col = colbase + wn * 32 + nf * 8 + tig * 2;
#pragma unroll
            for (int hf = 0; hf < 2; hf++) {
                float vx = acc[mf][nf][hf * 2], vy = acc[mf][nf][hf * 2 + 1];
                uint32_t H = packh2(__float2half_rn(vx), __float2half_rn(vy));
                __half* orow = Oe + (rowbase + r0 + hf * 8) * OEXT;
                *(uint32_t*)(orow + col)        = H;
                *(uint32_t*)(orow + 1024 + col) = H;
            }
        }
    }
}

// ---------------------------------------------------------------------------
extern "C" void kernel_launch(void* const* d_in, const int* in_sizes, int n_in,
                              void* d_out, int out_size)
{
    const float* x  = (const float*)d_in[0];
    const float* Wq = (const float*)d_in[1];
    const float* bq = (const float*)d_in[2];
    const float* Wk = (const float*)d_in[3];
    const float* bk = (const float*)d_in[4];
    const float* Wv = (const float*)d_in[5];
    const float* bv = (const float*)d_in[6];
    const float* Wo = (const float*)d_in[7];
    const float* bo = (const float*)d_in[8];
    const float* tw = (const float*)d_in[9];
    const float* fw = (const float*)d_in[10];

    float* out  = (float*)d_out;
    float* attn = out + (size_t)Mm * Dd;

    float *qaug, *kaug, *freq, *pmax, *psum, *rowm, *rowz;
    __half *qe, *ke, *v16, *xe, *oe, *stage;
    cudaGetSymbolAddress((void**)&qaug,  g_Qaug);
    cudaGetSymbolAddress((void**)&kaug,  g_Kaug);
    cudaGetSymbolAddress((void**)&qe,    g_Qe16);
    cudaGetSymbolAddress((void**)&ke,    g_Ke16);
    cudaGetSymbolAddress((void**)&v16,   g_V16);
    cudaGetSymbolAddress((void**)&freq,  g_Freq);
    cudaGetSymbolAddress((void**)&stage, g_Stage);
    cudaGetSymbolAddress((void**)&xe,    g_Xext);
    cudaGetSymbolAddress((void**)&oe,    g_Oext);
    cudaGetSymbolAddress((void**)&pmax,  g_pmax);
    cudaGetSymbolAddress((void**)&psum,  g_psum);
    cudaGetSymbolAddress((void**)&rowm,  g_rowm);
    cudaGetSymbolAddress((void**)&rowz,  g_rowz);

    cudaFuncSetAttribute(scores16_k<192, 12, 0>,
                         cudaFuncAttributeMaxDynamicSharedMemorySize, SMPIPE);
    cudaFuncSetAttribute(scores16_k<0, 6, 1>,
                         cudaFuncAttributeMaxDynamicSharedMemorySize, SMPIPE);
    cudaFuncSetAttribute(gemm16qkv_k, cudaFuncAttributeMaxDynamicSharedMemorySize, SMPIPE);
    cudaFuncSetAttribute(gemm16o_k,   cudaFuncAttributeMaxDynamicSharedMemorySize, SMPIPE);

    dim3 blk(256);

    twiddle_init_k<<<4, 256>>>();

    // ext conversions
    convx_k<<<Mm, 256>>>(x, xe);
    convw_k<<<dim3(Dd, 4), 256>>>(Wq, Wk, Wv, Wo);

    // merged Q/K/V projections
    gemm16qkv_k<<<dim3(4, 32, 3), blk, SMPIPE>>>(xe, bq, bk, bv, qaug, kaug, v16);

    // FFT
    fft_k<<<dim3(BHh, 2, 32), blk>>>(qaug, kaug, tw, fw);

    // fp16x2 split for scores
    {
        int nblk = (int)(((size_t)BHh * Ss * 48) / 256);
        convert16_k<1><<<nblk, 256>>>(qaug, qe);
        convert16_k<0><<<nblk, 256>>>(kaug, ke);
    }

    // freq scores rows 0..1024 -> staged fp32
    scores16_k<192, 12, 0><<<dim3(8, 9, BHh), blk, SMPIPE>>>(qe, ke, stage, freq, pmax, psum);

    // time scores + freq add -> fp16 delta staging + softmax partials
    scores16_k<0, 6, 1><<<dim3(8, 16, BHh), blk, SMPIPE>>>(qe, ke, stage, freq, pmax, psum);

    // combine partials
    combine_k<<<(BHh * Ss) / 256, 256>>>(pmax, psum, rowm, rowz);

    // fused normalize + attn*V (reads fp16 deltas, writes fp32 attn + O)
    attnv16_k<<<dim3(16, BHh), blk>>>(stage, attn, v16, rowm, rowz, pmax, oe);

    // out projection (K=2048 over [Wh|Wl])
    gemm16o_k<<<dim3(4, 32), blk, SMPIPE>>>(oe, bo, out);
}